// round 9
// baseline (speedup 1.0000x reference)
#include <cuda_runtime.h>
#include <cuda_bf16.h>
#include <math.h>
#include <stdint.h>

#define BB   2
#define LL   1024
#define DIMM 768
#define DI   1536
#define DS   16
#define DTR  48
#define NX   80   // DTR + 2*DS
#define NXP  128  // padded N for xdbl HMMA
#define TT   64   // scan time tile

typedef __nv_bfloat16 bf16;

// ---------------- device scratch ----------------
__device__ float g_xz   [2 * BB * LL * 2 * DI];   // [dir][m][3072]
__device__ float g_xc   [2 * BB * LL * DI];
__device__ float g_xdbl [2 * BB * LL * NX];
__device__ float g_dt   [2 * BB * LL * DI];

__device__ bf16 g_x_h  [BB * LL * DIMM];
__device__ bf16 g_x_l  [BB * LL * DIMM];
__device__ bf16 g_win_h[2 * 2 * DI * DIMM];
__device__ bf16 g_win_l[2 * 2 * DI * DIMM];
__device__ bf16 g_wout_h[2 * DIMM * DI];
__device__ bf16 g_wout_l[2 * DIMM * DI];
__device__ bf16 g_wx_h [2 * NXP * DI];            // zero-padded rows 80..127
__device__ bf16 g_wx_l [2 * NXP * DI];
__device__ bf16 g_xc_h [2 * BB * LL * DI];
__device__ bf16 g_xc_l [2 * BB * LL * DI];
__device__ bf16 g_y_h  [2 * BB * LL * DI];
__device__ bf16 g_y_l  [2 * BB * LL * DI];

__device__ __forceinline__ int fliprow(int m) {
    return (m & ~1023) + (1023 - (m & 1023));
}

__device__ __forceinline__ uint32_t smem_u32(const void* p) {
    uint32_t a;
    asm("{ .reg .u64 t; cvta.to.shared.u64 t, %1; cvt.u32.u64 %0, t; }" : "=r"(a) : "l"(p));
    return a;
}

__device__ __forceinline__ void ldmx4(uint32_t* r, uint32_t addr) {
    asm volatile("ldmatrix.sync.aligned.m8n8.x4.shared.b16 {%0,%1,%2,%3}, [%4];"
        : "=r"(r[0]), "=r"(r[1]), "=r"(r[2]), "=r"(r[3]) : "r"(addr));
}

__device__ __forceinline__ void mma16816(float* d, const uint32_t* a, const uint32_t* b) {
    asm volatile("mma.sync.aligned.m16n8k16.row.col.f32.bf16.bf16.f32 "
        "{%0,%1,%2,%3}, {%4,%5,%6,%7}, {%8,%9}, {%0,%1,%2,%3};"
        : "+f"(d[0]), "+f"(d[1]), "+f"(d[2]), "+f"(d[3])
        : "r"(a[0]), "r"(a[1]), "r"(a[2]), "r"(a[3]), "r"(b[0]), "r"(b[1]));
}

__device__ __forceinline__ void cp_async16(uint32_t dst, const void* src) {
    asm volatile("cp.async.cg.shared.global [%0], [%1], 16;" :: "r"(dst), "l"(src));
}
__device__ __forceinline__ void cp_commit() {
    asm volatile("cp.async.commit_group;" ::: "memory");
}
template<int N>
__device__ __forceinline__ void cp_wait() {
    asm volatile("cp.async.wait_group %0;" :: "n"(N) : "memory");
}

// =======================================================================
// HMMA bf16 split GEMM: fused 3-product K-chunks (Ah*Wh + Al*Wh + Ah*Wl),
// 3-stage cp.async ring, ONE __syncthreads per chunk.
// MODE 0 (xz):   dir = blockIdx.z; A = x (flip if dir), C[dir]
// MODE 1 (wout): C = X + sum_dir A(y[dir], flip if dir) @ W[dir]^T
// MODE 2 (xdbl): dir = blockIdx.z; A = xc[dir] (no flip), store cols < NX only
// BN=128, BK=32, K%32==0.
// =======================================================================
template<int MODE, int BM>
__global__ void __launch_bounds__(256)
mma_gemm(const bf16* __restrict__ Ah, const bf16* __restrict__ Al,
         const bf16* __restrict__ Wh, const bf16* __restrict__ Wl,
         float* __restrict__ C, const float* __restrict__ X,
         int K, int ldc, size_t aDirStride, size_t wDirStride, size_t cDirStride)
{
    constexpr int NWM = BM / 32;
    constexpr int NWN = 8 / NWM;
    constexpr int WNW = 128 / NWN;
    constexpr int NAT = WNW / 8;
    constexpr int AV  = BM * 4 / 256;     // vec16 per thread per A tile
    constexpr int ARS = 80;               // smem row stride (bytes)
    constexpr int T_AH = 0;
    constexpr int T_AL = BM * ARS;
    constexpr int T_WH = 2 * BM * ARS;
    constexpr int T_WL = 2 * BM * ARS + 128 * ARS;
    constexpr int STAGE = (2 * BM + 256) * ARS;

    extern __shared__ __align__(128) unsigned char smem[];
    const uint32_t smem_u = smem_u32(smem);

    const int tid  = threadIdx.x;
    const int wid  = tid >> 5;
    const int lane = tid & 31;
    const int warp_m = wid % NWM;
    const int warp_n = wid / NWM;
    const int m0 = blockIdx.y * BM;
    const int n0 = blockIdx.x * 128;

    // ldmatrix per-lane offsets relative to tile base
    const int quad = lane >> 3, liq = lane & 7;
    const int khB = (quad >> 1) * 16;
    uint32_t aOff[2], bOff[NAT / 2];
#pragma unroll
    for (int ma = 0; ma < 2; ma++) {
        int r = warp_m * 32 + ma * 16 + (quad & 1) * 8 + liq;
        aOff[ma] = r * ARS + khB;
    }
#pragma unroll
    for (int p = 0; p < NAT / 2; p++) {
        int r = warp_n * WNW + p * 16 + (quad & 1) * 8 + liq;
        bOff[p] = r * ARS + khB;
    }

    // cp.async coords
    int a_row[AV], a_c16[AV];
#pragma unroll
    for (int i = 0; i < AV; i++) {
        int v = tid + i * 256;
        a_row[i] = v >> 2; a_c16[i] = v & 3;
    }
    int b_row[2], b_c16[2];
#pragma unroll
    for (int i = 0; i < 2; i++) {
        int v = tid + i * 256;
        b_row[i] = v >> 2; b_c16[i] = v & 3;
    }

    float acc[2][NAT][4];
#pragma unroll
    for (int ma = 0; ma < 2; ma++)
#pragma unroll
        for (int na = 0; na < NAT; na++)
#pragma unroll
            for (int j = 0; j < 4; j++) acc[ma][na][j] = 0.f;

    const int chunksPerK = K / 32;
    const int total = (MODE == 1) ? 2 * chunksPerK : chunksPerK;

    auto issue_stage = [&](int c, int s) {
        const int dir = (MODE == 1) ? (c / chunksPerK) : blockIdx.z;
        const int kc = (c % chunksPerK) * 32;
        const bf16* AhP = Ah + (size_t)dir * aDirStride;
        const bf16* AlP = Al + (size_t)dir * aDirStride;
        const bf16* WhP = Wh + (size_t)dir * wDirStride;
        const bf16* WlP = Wl + (size_t)dir * wDirStride;
        const bool flip = (MODE != 2) && (dir == 1);
        const uint32_t base = smem_u + s * STAGE;
#pragma unroll
        for (int i = 0; i < AV; i++) {
            int m = m0 + a_row[i];
            int row = flip ? fliprow(m) : m;
            size_t go = (size_t)row * K + kc + a_c16[i] * 8;
            uint32_t so = a_row[i] * ARS + a_c16[i] * 16;
            cp_async16(base + T_AH + so, AhP + go);
            cp_async16(base + T_AL + so, AlP + go);
        }
#pragma unroll
        for (int i = 0; i < 2; i++) {
            size_t go = (size_t)(n0 + b_row[i]) * K + kc + b_c16[i] * 8;
            uint32_t so = b_row[i] * ARS + b_c16[i] * 16;
            cp_async16(base + T_WH + so, WhP + go);
            cp_async16(base + T_WL + so, WlP + go);
        }
        cp_commit();
    };

    issue_stage(0, 0);
    if (total > 1) issue_stage(1, 1);

    for (int c = 0; c < total; c++) {
        if (c + 1 < total) cp_wait<1>(); else cp_wait<0>();
        __syncthreads();
        if (c + 2 < total) issue_stage(c + 2, (c + 2) % 3);

        const uint32_t sbase = smem_u + (c % 3) * STAGE;
#pragma unroll
        for (int ks = 0; ks < 2; ks++) {
            const int ko = ks * 32;
            uint32_t ah[2][4], al[2][4];
            ldmx4(ah[0], sbase + T_AH + aOff[0] + ko);
            ldmx4(ah[1], sbase + T_AH + aOff[1] + ko);
            ldmx4(al[0], sbase + T_AL + aOff[0] + ko);
            ldmx4(al[1], sbase + T_AL + aOff[1] + ko);
            uint32_t bh[NAT][2], bl[NAT][2];
#pragma unroll
            for (int p = 0; p < NAT / 2; p++) {
                uint32_t r[4];
                ldmx4(r, sbase + T_WH + bOff[p] + ko);
                bh[2*p][0] = r[0]; bh[2*p][1] = r[2];
                bh[2*p+1][0] = r[1]; bh[2*p+1][1] = r[3];
                ldmx4(r, sbase + T_WL + bOff[p] + ko);
                bl[2*p][0] = r[0]; bl[2*p][1] = r[2];
                bl[2*p+1][0] = r[1]; bl[2*p+1][1] = r[3];
            }
#pragma unroll
            for (int ma = 0; ma < 2; ma++)
#pragma unroll
                for (int na = 0; na < NAT; na++) {
                    mma16816(acc[ma][na], ah[ma], bh[na]);
                    mma16816(acc[ma][na], al[ma], bh[na]);
                    mma16816(acc[ma][na], ah[ma], bl[na]);
                }
        }
    }

    // epilogue
    float* Cd = C + ((MODE == 1) ? 0 : (size_t)blockIdx.z * cDirStride);
#pragma unroll
    for (int ma = 0; ma < 2; ma++) {
#pragma unroll
        for (int na = 0; na < NAT; na++) {
            int row = m0 + warp_m * 32 + ma * 16 + (lane >> 2);
            int col = n0 + warp_n * WNW + na * 8 + 2 * (lane & 3);
            if (MODE == 2 && col >= NX) continue;
            float2 v0 = make_float2(acc[ma][na][0], acc[ma][na][1]);
            float2 v1 = make_float2(acc[ma][na][2], acc[ma][na][3]);
            if (MODE == 1) {
                float2 x0 = *(const float2*)&X[(size_t)row * ldc + col];
                float2 x1 = *(const float2*)&X[(size_t)(row + 8) * ldc + col];
                v0.x += x0.x; v0.y += x0.y; v1.x += x1.x; v1.y += x1.y;
            }
            *(float2*)&Cd[(size_t)row * ldc + col] = v0;
            *(float2*)&Cd[(size_t)(row + 8) * ldc + col] = v1;
        }
    }
}

// ==================== fused hi/lo split prep ====================
// 7 regions; regions may zero-pad beyond srcN4 (used for W_x row padding).
struct SplitArgs {
    const float* src[7];
    bf16* hi[7];
    bf16* lo[7];
    int n4[7];
    int srcN4[7];
};

__global__ void split_all_kernel(SplitArgs a)
{
    const int r = blockIdx.y;
    int i = blockIdx.x * blockDim.x + threadIdx.x;
    if (i >= a.n4[r]) return;
    float4 v = (i < a.srcN4[r]) ? ((const float4*)a.src[r])[i]
                                : make_float4(0.f, 0.f, 0.f, 0.f);
    bf16 h0 = __float2bfloat16(v.x), h1 = __float2bfloat16(v.y);
    bf16 h2 = __float2bfloat16(v.z), h3 = __float2bfloat16(v.w);
    bf16 l0 = __float2bfloat16(v.x - __bfloat162float(h0));
    bf16 l1 = __float2bfloat16(v.y - __bfloat162float(h1));
    bf16 l2 = __float2bfloat16(v.z - __bfloat162float(h2));
    bf16 l3 = __float2bfloat16(v.w - __bfloat162float(h3));
    ((__nv_bfloat162*)a.hi[r])[2*i]   = __nv_bfloat162(h0, h1);
    ((__nv_bfloat162*)a.hi[r])[2*i+1] = __nv_bfloat162(h2, h3);
    ((__nv_bfloat162*)a.lo[r])[2*i]   = __nv_bfloat162(l0, l1);
    ((__nv_bfloat162*)a.lo[r])[2*i+1] = __nv_bfloat162(l2, l3);
}

// ==================== SIMT GEMM for dt (K=48) ====================
template<int BM, int BN, int BK, int TM, int TN>
__global__ void __launch_bounds__((BM/TM)*(BN/TN), 2)
gemm_dt(const float* __restrict__ A, int lda, size_t aStride,
        const float* __restrict__ W0, const float* __restrict__ W1,
        float* __restrict__ C, int ldc, size_t cStride,
        int M, int N, int K,
        const float* __restrict__ bias0, const float* __restrict__ bias1)
{
    constexpr int THREADS = (BM/TM)*(BN/TN);
    constexpr int AF4 = BM*BK/4/THREADS;
    constexpr int BF4 = BN*BK/4/THREADS;
    __shared__ float As[BK][BM+4];
    __shared__ float Bs[BK][BN+4];

    const int tid = threadIdx.x;
    const int tx  = tid % (BN/TN);
    const int ty  = tid / (BN/TN);
    const int m0  = blockIdx.y * BM;
    const int n0  = blockIdx.x * BN;
    const int dir = blockIdx.z;

    const float* Ab = A + (size_t)dir * aStride;
    const float* W  = dir ? W1 : W0;
    const float* bias = dir ? bias1 : bias0;
    float* Cb = C + (size_t)dir * cStride;

    int a_mm[AF4], a_kk[AF4]; const float* a_ptr[AF4];
#pragma unroll
    for (int i = 0; i < AF4; i++) {
        int idx = tid + i * THREADS;
        a_mm[i] = idx / (BK/4); a_kk[i] = (idx % (BK/4)) * 4;
        a_ptr[i] = Ab + (size_t)(m0 + a_mm[i]) * lda + a_kk[i];
    }
    int b_nn[BF4], b_kk[BF4]; const float* b_ptr[BF4];
#pragma unroll
    for (int i = 0; i < BF4; i++) {
        int idx = tid + i * THREADS;
        b_nn[i] = idx / (BK/4); b_kk[i] = (idx % (BK/4)) * 4;
        b_ptr[i] = W + (size_t)(n0 + b_nn[i]) * K + b_kk[i];
    }

    float acc[TM][TN];
#pragma unroll
    for (int i = 0; i < TM; i++)
#pragma unroll
        for (int j = 0; j < TN; j++) acc[i][j] = 0.f;

    for (int k0 = 0; k0 < K; k0 += BK) {
#pragma unroll
        for (int i = 0; i < AF4; i++) {
            float4 v = *(const float4*)(a_ptr[i] + k0);
            As[a_kk[i]+0][a_mm[i]] = v.x; As[a_kk[i]+1][a_mm[i]] = v.y;
            As[a_kk[i]+2][a_mm[i]] = v.z; As[a_kk[i]+3][a_mm[i]] = v.w;
        }
#pragma unroll
        for (int i = 0; i < BF4; i++) {
            float4 v = *(const float4*)(b_ptr[i] + k0);
            Bs[b_kk[i]+0][b_nn[i]] = v.x; Bs[b_kk[i]+1][b_nn[i]] = v.y;
            Bs[b_kk[i]+2][b_nn[i]] = v.z; Bs[b_kk[i]+3][b_nn[i]] = v.w;
        }
        __syncthreads();
#pragma unroll
        for (int kk = 0; kk < BK; kk++) {
            float a[TM], b[TN];
#pragma unroll
            for (int i = 0; i < TM; i += 4) {
                float4 v = *(const float4*)&As[kk][ty*TM + i];
                a[i] = v.x; a[i+1] = v.y; a[i+2] = v.z; a[i+3] = v.w;
            }
#pragma unroll
            for (int j = 0; j < TN; j += 4) {
                float4 v = *(const float4*)&Bs[kk][tx*TN + j];
                b[j] = v.x; b[j+1] = v.y; b[j+2] = v.z; b[j+3] = v.w;
            }
#pragma unroll
            for (int i = 0; i < TM; i++)
#pragma unroll
                for (int j = 0; j < TN; j++) acc[i][j] += a[i] * b[j];
        }
        __syncthreads();
    }

#pragma unroll
    for (int i = 0; i < TM; i++) {
        int m = m0 + ty*TM + i;
#pragma unroll
        for (int j = 0; j < TN; j += 4) {
            int n = n0 + tx*TN + j;
            float4 v = make_float4(acc[i][j], acc[i][j+1], acc[i][j+2], acc[i][j+3]);
            v.x += bias[n+0]; v.y += bias[n+1]; v.z += bias[n+2]; v.w += bias[n+3];
            v.x = (v.x > 20.f) ? v.x : log1pf(expf(v.x));
            v.y = (v.y > 20.f) ? v.y : log1pf(expf(v.y));
            v.z = (v.z > 20.f) ? v.z : log1pf(expf(v.z));
            v.w = (v.w > 20.f) ? v.w : log1pf(expf(v.w));
            *(float4*)&Cb[(size_t)m * ldc + n] = v;
        }
    }
}

// ==================== conv + silu (emits fp32 + bf16 hi/lo) ====================
__global__ void conv_silu_kernel(const float* __restrict__ cw_f, const float* __restrict__ cb_f,
                                 const float* __restrict__ cw_b, const float* __restrict__ cb_b)
{
    const int TOT4 = 2 * BB * LL * DI / 4;
    int idx = blockIdx.x * blockDim.x + threadIdx.x;
    if (idx >= TOT4) return;
    const int DQ = DI / 4;
    int dq = idx % DQ;
    int r = idx / DQ;
    int t = r % LL; r /= LL;
    int b = r % BB;
    int dir = r / BB;
    int d4 = dq * 4;
    const float* w  = dir ? cw_b : cw_f;
    const float* cb = dir ? cb_b : cb_f;
    const float* xp = g_xz + ((size_t)(dir * BB + b)) * LL * 2 * DI;

    float4 wr0 = *(const float4*)&w[(d4+0)*4];
    float4 wr1 = *(const float4*)&w[(d4+1)*4];
    float4 wr2 = *(const float4*)&w[(d4+2)*4];
    float4 wr3 = *(const float4*)&w[(d4+3)*4];
    float4 s = *(const float4*)&cb[d4];
#pragma unroll
    for (int k = 0; k < 4; k++) {
        int tt = t + k - 3;
        if (tt >= 0) {
            float4 xv = *(const float4*)&xp[(size_t)tt * 2 * DI + d4];
            s.x += ((const float*)&wr0)[k] * xv.x;
            s.y += ((const float*)&wr1)[k] * xv.y;
            s.z += ((const float*)&wr2)[k] * xv.z;
            s.w += ((const float*)&wr3)[k] * xv.w;
        }
    }
    s.x = s.x / (1.f + __expf(-s.x));
    s.y = s.y / (1.f + __expf(-s.y));
    s.z = s.z / (1.f + __expf(-s.z));
    s.w = s.w / (1.f + __expf(-s.w));
    ((float4*)g_xc)[idx] = s;

    bf16 h0 = __float2bfloat16(s.x), h1 = __float2bfloat16(s.y);
    bf16 h2 = __float2bfloat16(s.z), h3 = __float2bfloat16(s.w);
    ((__nv_bfloat162*)g_xc_h)[2*idx]   = __nv_bfloat162(h0, h1);
    ((__nv_bfloat162*)g_xc_h)[2*idx+1] = __nv_bfloat162(h2, h3);
    bf16 l0 = __float2bfloat16(s.x - __bfloat162float(h0));
    bf16 l1 = __float2bfloat16(s.y - __bfloat162float(h1));
    bf16 l2 = __float2bfloat16(s.z - __bfloat162float(h2));
    bf16 l3 = __float2bfloat16(s.w - __bfloat162float(h3));
    ((__nv_bfloat162*)g_xc_l)[2*idx]   = __nv_bfloat162(l0, l1);
    ((__nv_bfloat162*)g_xc_l)[2*idx+1] = __nv_bfloat162(l2, l3);
}

// ==================== selective scan (smem time-tiled) ====================
__global__ void __launch_bounds__(256)
scan_kernel(const float* __restrict__ Alog_f, const float* __restrict__ D_f,
            const float* __restrict__ Alog_b, const float* __restrict__ D_b)
{
    __shared__ float s_dt[TT][32], s_xc[TT][32], s_z[TT][32], s_bc[TT][32];
    __shared__ bf16  s_yh[TT][32], s_yl[TT][32];

    const int tid = threadIdx.x;
    const int s4 = tid & 7;
    const int dl = tid >> 3;
    const int d0  = blockIdx.x * 32;
    const int b   = blockIdx.y;
    const int dir = blockIdx.z;

    const float* Alog = dir ? Alog_b : Alog_f;
    const float* Dp   = dir ? D_b   : D_f;

    const size_t base_di = ((size_t)(dir * BB + b)) * LL * DI;
    const size_t base_x  = ((size_t)(dir * BB + b)) * LL * NX;
    const size_t base_z  = ((size_t)(dir * BB + b)) * LL * 2 * DI + DI;

    float2 Av = *(const float2*)&Alog[(d0 + dl) * DS + 2*s4];
    const float A0 = -__expf(Av.x);
    const float A1 = -__expf(Av.y);
    const float Dv = Dp[d0 + dl];

    float h0 = 0.f, h1 = 0.f;

    for (int t0 = 0; t0 < LL; t0 += TT) {
#pragma unroll
        for (int i = tid; i < TT * 32; i += 256) {
            int t = i >> 5, d = i & 31;
            size_t r = base_di + (size_t)(t0 + t) * DI + d0 + d;
            s_dt[t][d] = g_dt[r];
            s_xc[t][d] = g_xc[r];
            s_z [t][d] = g_xz[base_z + (size_t)(t0 + t) * 2 * DI + d0 + d];
            s_bc[t][d] = g_xdbl[base_x + (size_t)(t0 + t) * NX + DTR + d];
        }
        __syncthreads();

#pragma unroll 8
        for (int t = 0; t < TT; t++) {
            float dtv = s_dt[t][dl];
            float xcv = s_xc[t][dl];
            float B0 = s_bc[t][2*s4],      B1 = s_bc[t][2*s4 + 1];
            float C0 = s_bc[t][16 + 2*s4], C1 = s_bc[t][17 + 2*s4];
            float dx  = dtv * xcv;
            h0 = __expf(dtv * A0) * h0 + dx * B0;
            h1 = __expf(dtv * A1) * h1 + dx * B1;
            float p = h0 * C0 + h1 * C1;
            p += __shfl_xor_sync(0xffffffffu, p, 4);
            p += __shfl_xor_sync(0xffffffffu, p, 2);
            p += __shfl_xor_sync(0xffffffffu, p, 1);
            if (s4 == 0) {
                float zv = s_z[t][dl];
                float y = p + xcv * Dv;
                float sig = 1.f / (1.f + __expf(-zv));
                y = y * (zv * sig);
                bf16 h = __float2bfloat16(y);
                s_yh[t][dl] = h;
                s_yl[t][dl] = __float2bfloat16(y - __bfloat162float(h));
            }
        }
        __syncthreads();

#pragma unroll
        for (int i = tid; i < TT * 32; i += 256) {
            int t = i >> 5, d = i & 31;
            size_t r = base_di + (size_t)(t0 + t) * DI + d0 + d;
            g_y_h[r] = s_yh[t][d];
            g_y_l[r] = s_yl[t][d];
        }
        __syncthreads();
    }
}

static inline int cdiv(int a, int b) { return (a + b - 1) / b; }

extern "C" void kernel_launch(void* const* d_in, const int* in_sizes, int n_in,
                              void* d_out, int out_size)
{
    const float* x = (const float*)d_in[0];
    const float* W_in[2]   = { (const float*)d_in[1],  (const float*)d_in[10] };
    const float* conv_w[2] = { (const float*)d_in[2],  (const float*)d_in[11] };
    const float* conv_b[2] = { (const float*)d_in[3],  (const float*)d_in[12] };
    const float* W_x[2]    = { (const float*)d_in[4],  (const float*)d_in[13] };
    const float* W_dt[2]   = { (const float*)d_in[5],  (const float*)d_in[14] };
    const float* b_dt[2]   = { (const float*)d_in[6],  (const float*)d_in[15] };
    const float* A_log[2]  = { (const float*)d_in[7],  (const float*)d_in[16] };
    const float* Dvec[2]   = { (const float*)d_in[8],  (const float*)d_in[17] };
    const float* W_out[2]  = { (const float*)d_in[9],  (const float*)d_in[18] };
    float* out = (float*)d_out;

    float *p_xz, *p_xdbl, *p_dt;
    cudaGetSymbolAddress((void**)&p_xz,   g_xz);
    cudaGetSymbolAddress((void**)&p_xdbl, g_xdbl);
    cudaGetSymbolAddress((void**)&p_dt,   g_dt);
    bf16 *p_xh, *p_xl, *p_winh, *p_winl, *p_wouth, *p_woutl;
    bf16 *p_wxh, *p_wxl, *p_xch, *p_xcl, *p_yh, *p_yl;
    cudaGetSymbolAddress((void**)&p_xh,    g_x_h);
    cudaGetSymbolAddress((void**)&p_xl,    g_x_l);
    cudaGetSymbolAddress((void**)&p_winh,  g_win_h);
    cudaGetSymbolAddress((void**)&p_winl,  g_win_l);
    cudaGetSymbolAddress((void**)&p_wouth, g_wout_h);
    cudaGetSymbolAddress((void**)&p_woutl, g_wout_l);
    cudaGetSymbolAddress((void**)&p_wxh,   g_wx_h);
    cudaGetSymbolAddress((void**)&p_wxl,   g_wx_l);
    cudaGetSymbolAddress((void**)&p_xch,   g_xc_h);
    cudaGetSymbolAddress((void**)&p_xcl,   g_xc_l);
    cudaGetSymbolAddress((void**)&p_yh,    g_y_h);
    cudaGetSymbolAddress((void**)&p_yl,    g_y_l);

    const int M = BB * LL;  // 2048

    const int SMEM_G0 = 3 * (2 * 128 + 256) * 80;   // 122880
    const int SMEM_G1 = 3 * (2 * 64 + 256) * 80;    // 92160
    cudaFuncSetAttribute(mma_gemm<0,128>, cudaFuncAttributeMaxDynamicSharedMemorySize, SMEM_G0);
    cudaFuncSetAttribute(mma_gemm<1,64>,  cudaFuncAttributeMaxDynamicSharedMemorySize, SMEM_G1);
    cudaFuncSetAttribute(mma_gemm<2,64>,  cudaFuncAttributeMaxDynamicSharedMemorySize, SMEM_G1);

    // 0) hi/lo splits (one launch, 7 regions; W_x zero-padded to 128 rows)
    {
        SplitArgs a;
        a.src[0] = x;        a.hi[0] = p_xh;    a.lo[0] = p_xl;
        a.n4[0] = M * DIMM / 4;            a.srcN4[0] = a.n4[0];
        a.src[1] = W_in[0];  a.hi[1] = p_winh;  a.lo[1] = p_winl;
        a.n4[1] = 2 * DI * DIMM / 4;       a.srcN4[1] = a.n4[1];
        a.src[2] = W_in[1];  a.hi[2] = p_winh + (size_t)2*DI*DIMM;
                             a.lo[2] = p_winl + (size_t)2*DI*DIMM;
        a.n4[2] = 2 * DI * DIMM / 4;       a.srcN4[2] = a.n4[2];
        a.src[3] = W_out[0]; a.hi[3] = p_wouth; a.lo[3] = p_woutl;
        a.n4[3] = DIMM * DI / 4;           a.srcN4[3] = a.n4[3];
        a.src[4] = W_out[1]; a.hi[4] = p_wouth + (size_t)DIMM*DI;
                             a.lo[4] = p_woutl + (size_t)DIMM*DI;
        a.n4[4] = DIMM * DI / 4;           a.srcN4[4] = a.n4[4];
        a.src[5] = W_x[0];   a.hi[5] = p_wxh;   a.lo[5] = p_wxl;
        a.n4[5] = NXP * DI / 4;            a.srcN4[5] = NX * DI / 4;
        a.src[6] = W_x[1];   a.hi[6] = p_wxh + (size_t)NXP*DI;
                             a.lo[6] = p_wxl + (size_t)NXP*DI;
        a.n4[6] = NXP * DI / 4;            a.srcN4[6] = NX * DI / 4;
        int maxn4 = 2 * DI * DIMM / 4;
        dim3 grid(cdiv(maxn4, 256), 7);
        split_all_kernel<<<grid, 256>>>(a);
    }

    // 1) xz = x(+flip) @ W_in^T  (HMMA, 3-stage)
    {
        dim3 grid(2 * DI / 128, M / 128, 2);
        mma_gemm<0, 128><<<grid, 256, SMEM_G0>>>(
            p_xh, p_xl, p_winh, p_winl,
            p_xz, nullptr,
            DIMM, 2 * DI,
            0, (size_t)2*DI*DIMM, (size_t)M * 2 * DI);
    }

    // 2) conv + silu -> g_xc (fp32 + bf16 hi/lo)
    {
        int n4 = 2 * BB * LL * DI / 4;
        conv_silu_kernel<<<cdiv(n4, 256), 256>>>(conv_w[0], conv_b[0], conv_w[1], conv_b[1]);
    }

    // 3) x_dbl = xc @ W_x^T  (HMMA MODE 2, padded N)
    {
        dim3 grid(1, M / 64, 2);
        mma_gemm<2, 64><<<grid, 256, SMEM_G1>>>(
            p_xch, p_xcl, p_wxh, p_wxl,
            p_xdbl, nullptr,
            DI, NX,
            (size_t)M * DI, (size_t)NXP * DI, (size_t)M * NX);
    }

    // 4) dt = softplus(x_dbl[:, :48] @ W_dt^T + b_dt)
    {
        dim3 grid(DI / 128, M / 128, 2);
        gemm_dt<128,128,16,8,8><<<grid, 256>>>(
            p_xdbl, NX, (size_t)M * NX,
            W_dt[0], W_dt[1],
            p_dt, DI, (size_t)M * DI,
            M, DI, DTR, b_dt[0], b_dt[1]);
    }

    // 5) selective scan + gating -> y hi/lo
    {
        dim3 grid(DI / 32, BB, 2);
        scan_kernel<<<grid, 256>>>(A_log[0], Dvec[0], A_log[1], Dvec[1]);
    }

    // 6) out = x + y0 @ W0^T + flip(y1) @ W1^T  (HMMA, 3-stage)
    {
        dim3 grid(DIMM / 128, M / 64, 1);
        mma_gemm<1, 64><<<grid, 256, SMEM_G1>>>(
            p_yh, p_yl, p_wouth, p_woutl,
            out, x,
            DI, DIMM,
            (size_t)M * DI, (size_t)DIMM * DI, 0);
    }

    (void)in_sizes; (void)n_in; (void)out_size;
}

// round 11
// speedup vs baseline: 1.0433x; 1.0433x over previous
#include <cuda_runtime.h>
#include <cuda_bf16.h>
#include <math.h>
#include <stdint.h>

#define BB   2
#define LL   1024
#define DIMM 768
#define DI   1536
#define DS   16
#define DTR  48
#define NX   80   // DTR + 2*DS
#define NXP  128  // padded N for xdbl HMMA
#define TT   64   // scan time tile

typedef __nv_bfloat16 bf16;

// ---------------- device scratch ----------------
__device__ float g_xz   [2 * BB * LL * 2 * DI];   // [dir][m][3072]
__device__ float g_xc   [2 * BB * LL * DI];
__device__ float g_xdbl [2 * BB * LL * NX];
__device__ float g_xdblp[2 * 2 * BB * LL * NX];   // [ksplit][dir][m][nx]
__device__ float g_dt   [2 * BB * LL * DI];

__device__ bf16 g_x_h  [BB * LL * DIMM];
__device__ bf16 g_x_l  [BB * LL * DIMM];
__device__ bf16 g_win_h[2 * 2 * DI * DIMM];
__device__ bf16 g_win_l[2 * 2 * DI * DIMM];
__device__ bf16 g_wout_h[2 * DIMM * DI];
__device__ bf16 g_wout_l[2 * DIMM * DI];
__device__ bf16 g_wx_h [2 * NXP * DI];            // zero-padded rows 80..127
__device__ bf16 g_wx_l [2 * NXP * DI];
__device__ bf16 g_xc_h [2 * BB * LL * DI];
__device__ bf16 g_xc_l [2 * BB * LL * DI];
__device__ bf16 g_y_h  [2 * BB * LL * DI];
__device__ bf16 g_y_l  [2 * BB * LL * DI];

__device__ __forceinline__ int fliprow(int m) {
    return (m & ~1023) + (1023 - (m & 1023));
}

__device__ __forceinline__ uint32_t smem_u32(const void* p) {
    uint32_t a;
    asm("{ .reg .u64 t; cvta.to.shared.u64 t, %1; cvt.u32.u64 %0, t; }" : "=r"(a) : "l"(p));
    return a;
}

__device__ __forceinline__ void ldmx4(uint32_t* r, uint32_t addr) {
    asm volatile("ldmatrix.sync.aligned.m8n8.x4.shared.b16 {%0,%1,%2,%3}, [%4];"
        : "=r"(r[0]), "=r"(r[1]), "=r"(r[2]), "=r"(r[3]) : "r"(addr));
}

__device__ __forceinline__ void mma16816(float* d, const uint32_t* a, const uint32_t* b) {
    asm volatile("mma.sync.aligned.m16n8k16.row.col.f32.bf16.bf16.f32 "
        "{%0,%1,%2,%3}, {%4,%5,%6,%7}, {%8,%9}, {%0,%1,%2,%3};"
        : "+f"(d[0]), "+f"(d[1]), "+f"(d[2]), "+f"(d[3])
        : "r"(a[0]), "r"(a[1]), "r"(a[2]), "r"(a[3]), "r"(b[0]), "r"(b[1]));
}

__device__ __forceinline__ void cp_async16(uint32_t dst, const void* src) {
    asm volatile("cp.async.cg.shared.global [%0], [%1], 16;" :: "r"(dst), "l"(src));
}
__device__ __forceinline__ void cp_commit() {
    asm volatile("cp.async.commit_group;" ::: "memory");
}
template<int N>
__device__ __forceinline__ void cp_wait() {
    asm volatile("cp.async.wait_group %0;" :: "n"(N) : "memory");
}

// =======================================================================
// HMMA bf16 split GEMM: fused 3-product K-chunks (Ah*Wh + Al*Wh + Ah*Wl),
// 2-stage cp.async ring (2 CTAs/SM for cross-CTA overlap).
// Pass-major mma ordering to break accumulator RAW chains.
// MODE 0 (xz):   dir = blockIdx.z; A = x (flip if dir), C[dir]
// MODE 1 (wout): C = X + sum_dir A(y[dir], flip if dir) @ W[dir]^T
// MODE 2 (xdbl): dir = blockIdx.z; ksplit = blockIdx.x (n0=0);
//                partial C slab [ksplit*2+dir], store cols < NX only
// BN=128, BK=32, K%32==0.
// =======================================================================
template<int MODE, int BM>
__global__ void __launch_bounds__(256)
mma_gemm(const bf16* __restrict__ Ah, const bf16* __restrict__ Al,
         const bf16* __restrict__ Wh, const bf16* __restrict__ Wl,
         float* __restrict__ C, const float* __restrict__ X,
         int K, int ldc, size_t aDirStride, size_t wDirStride, size_t cDirStride)
{
    constexpr int NWM = BM / 32;
    constexpr int NWN = 8 / NWM;
    constexpr int WNW = 128 / NWN;
    constexpr int NAT = WNW / 8;
    constexpr int AV  = BM * 4 / 256;     // vec16 per thread per A tile
    constexpr int ARS = 80;               // smem row stride (bytes)
    constexpr int T_AH = 0;
    constexpr int T_AL = BM * ARS;
    constexpr int T_WH = 2 * BM * ARS;
    constexpr int T_WL = 2 * BM * ARS + 128 * ARS;
    constexpr int STAGE = (2 * BM + 256) * ARS;

    extern __shared__ __align__(128) unsigned char smem[];
    const uint32_t smem_u = smem_u32(smem);

    const int tid  = threadIdx.x;
    const int wid  = tid >> 5;
    const int lane = tid & 31;
    const int warp_m = wid % NWM;
    const int warp_n = wid / NWM;
    const int m0 = blockIdx.y * BM;
    const int n0 = (MODE == 2) ? 0 : blockIdx.x * 128;

    // ldmatrix per-lane offsets relative to tile base
    const int quad = lane >> 3, liq = lane & 7;
    const int khB = (quad >> 1) * 16;
    uint32_t aOff[2], bOff[NAT / 2];
#pragma unroll
    for (int ma = 0; ma < 2; ma++) {
        int r = warp_m * 32 + ma * 16 + (quad & 1) * 8 + liq;
        aOff[ma] = r * ARS + khB;
    }
#pragma unroll
    for (int p = 0; p < NAT / 2; p++) {
        int r = warp_n * WNW + p * 16 + (quad & 1) * 8 + liq;
        bOff[p] = r * ARS + khB;
    }

    // cp.async coords
    int a_row[AV], a_c16[AV];
#pragma unroll
    for (int i = 0; i < AV; i++) {
        int v = tid + i * 256;
        a_row[i] = v >> 2; a_c16[i] = v & 3;
    }
    int b_row[2], b_c16[2];
#pragma unroll
    for (int i = 0; i < 2; i++) {
        int v = tid + i * 256;
        b_row[i] = v >> 2; b_c16[i] = v & 3;
    }

    float acc[2][NAT][4];
#pragma unroll
    for (int ma = 0; ma < 2; ma++)
#pragma unroll
        for (int na = 0; na < NAT; na++)
#pragma unroll
            for (int j = 0; j < 4; j++) acc[ma][na][j] = 0.f;

    const int chunksPerK = (MODE == 2) ? (K / 64) : (K / 32);  // MODE2: half-K chain
    const int total = (MODE == 1) ? 2 * chunksPerK : chunksPerK;
    const int kbase = (MODE == 2) ? blockIdx.x * (K / 2) : 0;

    auto issue_stage = [&](int c, int s) {
        const int dir = (MODE == 1) ? (c / chunksPerK) : blockIdx.z;
        const int kc = kbase + (c % chunksPerK) * 32;
        const bf16* AhP = Ah + (size_t)dir * aDirStride;
        const bf16* AlP = Al + (size_t)dir * aDirStride;
        const bf16* WhP = Wh + (size_t)dir * wDirStride;
        const bf16* WlP = Wl + (size_t)dir * wDirStride;
        const bool flip = (MODE != 2) && (dir == 1);
        const uint32_t base = smem_u + s * STAGE;
#pragma unroll
        for (int i = 0; i < AV; i++) {
            int m = m0 + a_row[i];
            int row = flip ? fliprow(m) : m;
            size_t go = (size_t)row * K + kc + a_c16[i] * 8;
            uint32_t so = a_row[i] * ARS + a_c16[i] * 16;
            cp_async16(base + T_AH + so, AhP + go);
            cp_async16(base + T_AL + so, AlP + go);
        }
#pragma unroll
        for (int i = 0; i < 2; i++) {
            size_t go = (size_t)(n0 + b_row[i]) * K + kc + b_c16[i] * 8;
            uint32_t so = b_row[i] * ARS + b_c16[i] * 16;
            cp_async16(base + T_WH + so, WhP + go);
            cp_async16(base + T_WL + so, WlP + go);
        }
        cp_commit();
    };

    issue_stage(0, 0);

    for (int c = 0; c < total; c++) {
        if (c + 1 < total) { issue_stage(c + 1, (c + 1) & 1); cp_wait<1>(); }
        else               { cp_wait<0>(); }
        __syncthreads();

        const uint32_t sbase = smem_u + (c & 1) * STAGE;
#pragma unroll
        for (int ks = 0; ks < 2; ks++) {
            const int ko = ks * 32;
            uint32_t ah[2][4], al[2][4];
            ldmx4(ah[0], sbase + T_AH + aOff[0] + ko);
            ldmx4(ah[1], sbase + T_AH + aOff[1] + ko);
            ldmx4(al[0], sbase + T_AL + aOff[0] + ko);
            ldmx4(al[1], sbase + T_AL + aOff[1] + ko);
            uint32_t bh[NAT][2], bl[NAT][2];
#pragma unroll
            for (int p = 0; p < NAT / 2; p++) {
                uint32_t r[4];
                ldmx4(r, sbase + T_WH + bOff[p] + ko);
                bh[2*p][0] = r[0]; bh[2*p][1] = r[2];
                bh[2*p+1][0] = r[1]; bh[2*p+1][1] = r[3];
                ldmx4(r, sbase + T_WL + bOff[p] + ko);
                bl[2*p][0] = r[0]; bl[2*p][1] = r[2];
                bl[2*p+1][0] = r[1]; bl[2*p+1][1] = r[3];
            }
            // pass-major: all accumulators per product -> long RAW distance
#pragma unroll
            for (int ma = 0; ma < 2; ma++)
#pragma unroll
                for (int na = 0; na < NAT; na++)
                    mma16816(acc[ma][na], ah[ma], bh[na]);
#pragma unroll
            for (int ma = 0; ma < 2; ma++)
#pragma unroll
                for (int na = 0; na < NAT; na++)
                    mma16816(acc[ma][na], al[ma], bh[na]);
#pragma unroll
            for (int ma = 0; ma < 2; ma++)
#pragma unroll
                for (int na = 0; na < NAT; na++)
                    mma16816(acc[ma][na], ah[ma], bl[na]);
        }
        __syncthreads();
    }

    // epilogue
    float* Cd;
    if (MODE == 1)      Cd = C;
    else if (MODE == 2) Cd = C + (size_t)(blockIdx.x * 2 + blockIdx.z) * cDirStride;
    else                Cd = C + (size_t)blockIdx.z * cDirStride;
#pragma unroll
    for (int ma = 0; ma < 2; ma++) {
#pragma unroll
        for (int na = 0; na < NAT; na++) {
            int row = m0 + warp_m * 32 + ma * 16 + (lane >> 2);
            int col = n0 + warp_n * WNW + na * 8 + 2 * (lane & 3);
            if (MODE == 2 && col >= NX) continue;
            float2 v0 = make_float2(acc[ma][na][0], acc[ma][na][1]);
            float2 v1 = make_float2(acc[ma][na][2], acc[ma][na][3]);
            if (MODE == 1) {
                float2 x0 = *(const float2*)&X[(size_t)row * ldc + col];
                float2 x1 = *(const float2*)&X[(size_t)(row + 8) * ldc + col];
                v0.x += x0.x; v0.y += x0.y; v1.x += x1.x; v1.y += x1.y;
            }
            *(float2*)&Cd[(size_t)row * ldc + col] = v0;
            *(float2*)&Cd[(size_t)(row + 8) * ldc + col] = v1;
        }
    }
}

// ==================== xdbl partial reduce ====================
__global__ void xdbl_reduce_kernel()
{
    const int N4 = 2 * BB * LL * NX / 4;   // float4 count of one k-half
    int i = blockIdx.x * blockDim.x + threadIdx.x;
    if (i >= N4) return;
    const float4* P = (const float4*)g_xdblp;
    float4 a = P[i];
    float4 b = P[i + N4];
    a.x += b.x; a.y += b.y; a.z += b.z; a.w += b.w;
    ((float4*)g_xdbl)[i] = a;
}

// ==================== fused hi/lo split prep ====================
struct SplitArgs {
    const float* src[7];
    bf16* hi[7];
    bf16* lo[7];
    int n4[7];
    int srcN4[7];
};

__global__ void split_all_kernel(SplitArgs a)
{
    const int r = blockIdx.y;
    int i = blockIdx.x * blockDim.x + threadIdx.x;
    if (i >= a.n4[r]) return;
    float4 v = (i < a.srcN4[r]) ? ((const float4*)a.src[r])[i]
                                : make_float4(0.f, 0.f, 0.f, 0.f);
    bf16 h0 = __float2bfloat16(v.x), h1 = __float2bfloat16(v.y);
    bf16 h2 = __float2bfloat16(v.z), h3 = __float2bfloat16(v.w);
    bf16 l0 = __float2bfloat16(v.x - __bfloat162float(h0));
    bf16 l1 = __float2bfloat16(v.y - __bfloat162float(h1));
    bf16 l2 = __float2bfloat16(v.z - __bfloat162float(h2));
    bf16 l3 = __float2bfloat16(v.w - __bfloat162float(h3));
    ((__nv_bfloat162*)a.hi[r])[2*i]   = __nv_bfloat162(h0, h1);
    ((__nv_bfloat162*)a.hi[r])[2*i+1] = __nv_bfloat162(h2, h3);
    ((__nv_bfloat162*)a.lo[r])[2*i]   = __nv_bfloat162(l0, l1);
    ((__nv_bfloat162*)a.lo[r])[2*i+1] = __nv_bfloat162(l2, l3);
}

// ==================== SIMT GEMM for dt (K=48) ====================
template<int BM, int BN, int BK, int TM, int TN>
__global__ void __launch_bounds__((BM/TM)*(BN/TN), 2)
gemm_dt(const float* __restrict__ A, int lda, size_t aStride,
        const float* __restrict__ W0, const float* __restrict__ W1,
        float* __restrict__ C, int ldc, size_t cStride,
        int M, int N, int K,
        const float* __restrict__ bias0, const float* __restrict__ bias1)
{
    constexpr int THREADS = (BM/TM)*(BN/TN);
    constexpr int AF4 = BM*BK/4/THREADS;
    constexpr int BF4 = BN*BK/4/THREADS;
    __shared__ float As[BK][BM+4];
    __shared__ float Bs[BK][BN+4];

    const int tid = threadIdx.x;
    const int tx  = tid % (BN/TN);
    const int ty  = tid / (BN/TN);
    const int m0  = blockIdx.y * BM;
    const int n0  = blockIdx.x * BN;
    const int dir = blockIdx.z;

    const float* Ab = A + (size_t)dir * aStride;
    const float* W  = dir ? W1 : W0;
    const float* bias = dir ? bias1 : bias0;
    float* Cb = C + (size_t)dir * cStride;

    int a_mm[AF4], a_kk[AF4]; const float* a_ptr[AF4];
#pragma unroll
    for (int i = 0; i < AF4; i++) {
        int idx = tid + i * THREADS;
        a_mm[i] = idx / (BK/4); a_kk[i] = (idx % (BK/4)) * 4;
        a_ptr[i] = Ab + (size_t)(m0 + a_mm[i]) * lda + a_kk[i];
    }
    int b_nn[BF4], b_kk[BF4]; const float* b_ptr[BF4];
#pragma unroll
    for (int i = 0; i < BF4; i++) {
        int idx = tid + i * THREADS;
        b_nn[i] = idx / (BK/4); b_kk[i] = (idx % (BK/4)) * 4;
        b_ptr[i] = W + (size_t)(n0 + b_nn[i]) * K + b_kk[i];
    }

    float acc[TM][TN];
#pragma unroll
    for (int i = 0; i < TM; i++)
#pragma unroll
        for (int j = 0; j < TN; j++) acc[i][j] = 0.f;

    for (int k0 = 0; k0 < K; k0 += BK) {
#pragma unroll
        for (int i = 0; i < AF4; i++) {
            float4 v = *(const float4*)(a_ptr[i] + k0);
            As[a_kk[i]+0][a_mm[i]] = v.x; As[a_kk[i]+1][a_mm[i]] = v.y;
            As[a_kk[i]+2][a_mm[i]] = v.z; As[a_kk[i]+3][a_mm[i]] = v.w;
        }
#pragma unroll
        for (int i = 0; i < BF4; i++) {
            float4 v = *(const float4*)(b_ptr[i] + k0);
            Bs[b_kk[i]+0][b_nn[i]] = v.x; Bs[b_kk[i]+1][b_nn[i]] = v.y;
            Bs[b_kk[i]+2][b_nn[i]] = v.z; Bs[b_kk[i]+3][b_nn[i]] = v.w;
        }
        __syncthreads();
#pragma unroll
        for (int kk = 0; kk < BK; kk++) {
            float a[TM], b[TN];
#pragma unroll
            for (int i = 0; i < TM; i += 4) {
                float4 v = *(const float4*)&As[kk][ty*TM + i];
                a[i] = v.x; a[i+1] = v.y; a[i+2] = v.z; a[i+3] = v.w;
            }
#pragma unroll
            for (int j = 0; j < TN; j += 4) {
                float4 v = *(const float4*)&Bs[kk][tx*TN + j];
                b[j] = v.x; b[j+1] = v.y; b[j+2] = v.z; b[j+3] = v.w;
            }
#pragma unroll
            for (int i = 0; i < TM; i++)
#pragma unroll
                for (int j = 0; j < TN; j++) acc[i][j] += a[i] * b[j];
        }
        __syncthreads();
    }

#pragma unroll
    for (int i = 0; i < TM; i++) {
        int m = m0 + ty*TM + i;
#pragma unroll
        for (int j = 0; j < TN; j += 4) {
            int n = n0 + tx*TN + j;
            float4 v = make_float4(acc[i][j], acc[i][j+1], acc[i][j+2], acc[i][j+3]);
            v.x += bias[n+0]; v.y += bias[n+1]; v.z += bias[n+2]; v.w += bias[n+3];
            v.x = (v.x > 20.f) ? v.x : log1pf(expf(v.x));
            v.y = (v.y > 20.f) ? v.y : log1pf(expf(v.y));
            v.z = (v.z > 20.f) ? v.z : log1pf(expf(v.z));
            v.w = (v.w > 20.f) ? v.w : log1pf(expf(v.w));
            *(float4*)&Cb[(size_t)m * ldc + n] = v;
        }
    }
}

// ==================== conv + silu (emits fp32 + bf16 hi/lo) ====================
__global__ void conv_silu_kernel(const float* __restrict__ cw_f, const float* __restrict__ cb_f,
                                 const float* __restrict__ cw_b, const float* __restrict__ cb_b)
{
    const int TOT4 = 2 * BB * LL * DI / 4;
    int idx = blockIdx.x * blockDim.x + threadIdx.x;
    if (idx >= TOT4) return;
    const int DQ = DI / 4;
    int dq = idx % DQ;
    int r = idx / DQ;
    int t = r % LL; r /= LL;
    int b = r % BB;
    int dir = r / BB;
    int d4 = dq * 4;
    const float* w  = dir ? cw_b : cw_f;
    const float* cb = dir ? cb_b : cb_f;
    const float* xp = g_xz + ((size_t)(dir * BB + b)) * LL * 2 * DI;

    float4 wr0 = *(const float4*)&w[(d4+0)*4];
    float4 wr1 = *(const float4*)&w[(d4+1)*4];
    float4 wr2 = *(const float4*)&w[(d4+2)*4];
    float4 wr3 = *(const float4*)&w[(d4+3)*4];
    float4 s = *(const float4*)&cb[d4];
#pragma unroll
    for (int k = 0; k < 4; k++) {
        int tt = t + k - 3;
        if (tt >= 0) {
            float4 xv = *(const float4*)&xp[(size_t)tt * 2 * DI + d4];
            s.x += ((const float*)&wr0)[k] * xv.x;
            s.y += ((const float*)&wr1)[k] * xv.y;
            s.z += ((const float*)&wr2)[k] * xv.z;
            s.w += ((const float*)&wr3)[k] * xv.w;
        }
    }
    s.x = s.x / (1.f + __expf(-s.x));
    s.y = s.y / (1.f + __expf(-s.y));
    s.z = s.z / (1.f + __expf(-s.z));
    s.w = s.w / (1.f + __expf(-s.w));
    ((float4*)g_xc)[idx] = s;

    bf16 h0 = __float2bfloat16(s.x), h1 = __float2bfloat16(s.y);
    bf16 h2 = __float2bfloat16(s.z), h3 = __float2bfloat16(s.w);
    ((__nv_bfloat162*)g_xc_h)[2*idx]   = __nv_bfloat162(h0, h1);
    ((__nv_bfloat162*)g_xc_h)[2*idx+1] = __nv_bfloat162(h2, h3);
    bf16 l0 = __float2bfloat16(s.x - __bfloat162float(h0));
    bf16 l1 = __float2bfloat16(s.y - __bfloat162float(h1));
    bf16 l2 = __float2bfloat16(s.z - __bfloat162float(h2));
    bf16 l3 = __float2bfloat16(s.w - __bfloat162float(h3));
    ((__nv_bfloat162*)g_xc_l)[2*idx]   = __nv_bfloat162(l0, l1);
    ((__nv_bfloat162*)g_xc_l)[2*idx+1] = __nv_bfloat162(l2, l3);
}

// ==================== selective scan (smem time-tiled) ====================
__global__ void __launch_bounds__(256)
scan_kernel(const float* __restrict__ Alog_f, const float* __restrict__ D_f,
            const float* __restrict__ Alog_b, const float* __restrict__ D_b)
{
    __shared__ float s_dt[TT][32], s_xc[TT][32], s_z[TT][32], s_bc[TT][32];
    __shared__ bf16  s_yh[TT][32], s_yl[TT][32];

    const int tid = threadIdx.x;
    const int s4 = tid & 7;
    const int dl = tid >> 3;
    const int d0  = blockIdx.x * 32;
    const int b   = blockIdx.y;
    const int dir = blockIdx.z;

    const float* Alog = dir ? Alog_b : Alog_f;
    const float* Dp   = dir ? D_b   : D_f;

    const size_t base_di = ((size_t)(dir * BB + b)) * LL * DI;
    const size_t base_x  = ((size_t)(dir * BB + b)) * LL * NX;
    const size_t base_z  = ((size_t)(dir * BB + b)) * LL * 2 * DI + DI;

    float2 Av = *(const float2*)&Alog[(d0 + dl) * DS + 2*s4];
    const float A0 = -__expf(Av.x);
    const float A1 = -__expf(Av.y);
    const float Dv = Dp[d0 + dl];

    float h0 = 0.f, h1 = 0.f;

    for (int t0 = 0; t0 < LL; t0 += TT) {
#pragma unroll
        for (int i = tid; i < TT * 32; i += 256) {
            int t = i >> 5, d = i & 31;
            size_t r = base_di + (size_t)(t0 + t) * DI + d0 + d;
            s_dt[t][d] = g_dt[r];
            s_xc[t][d] = g_xc[r];
            s_z [t][d] = g_xz[base_z + (size_t)(t0 + t) * 2 * DI + d0 + d];
            s_bc[t][d] = g_xdbl[base_x + (size_t)(t0 + t) * NX + DTR + d];
        }
        __syncthreads();

#pragma unroll 8
        for (int t = 0; t < TT; t++) {
            float dtv = s_dt[t][dl];
            float xcv = s_xc[t][dl];
            float B0 = s_bc[t][2*s4],      B1 = s_bc[t][2*s4 + 1];
            float C0 = s_bc[t][16 + 2*s4], C1 = s_bc[t][17 + 2*s4];
            float dx  = dtv * xcv;
            h0 = __expf(dtv * A0) * h0 + dx * B0;
            h1 = __expf(dtv * A1) * h1 + dx * B1;
            float p = h0 * C0 + h1 * C1;
            p += __shfl_xor_sync(0xffffffffu, p, 4);
            p += __shfl_xor_sync(0xffffffffu, p, 2);
            p += __shfl_xor_sync(0xffffffffu, p, 1);
            if (s4 == 0) {
                float zv = s_z[t][dl];
                float y = p + xcv * Dv;
                float sig = 1.f / (1.f + __expf(-zv));
                y = y * (zv * sig);
                bf16 h = __float2bfloat16(y);
                s_yh[t][dl] = h;
                s_yl[t][dl] = __float2bfloat16(y - __bfloat162float(h));
            }
        }
        __syncthreads();

#pragma unroll
        for (int i = tid; i < TT * 32; i += 256) {
            int t = i >> 5, d = i & 31;
            size_t r = base_di + (size_t)(t0 + t) * DI + d0 + d;
            g_y_h[r] = s_yh[t][d];
            g_y_l[r] = s_yl[t][d];
        }
        __syncthreads();
    }
}

static inline int cdiv(int a, int b) { return (a + b - 1) / b; }

extern "C" void kernel_launch(void* const* d_in, const int* in_sizes, int n_in,
                              void* d_out, int out_size)
{
    const float* x = (const float*)d_in[0];
    const float* W_in[2]   = { (const float*)d_in[1],  (const float*)d_in[10] };
    const float* conv_w[2] = { (const float*)d_in[2],  (const float*)d_in[11] };
    const float* conv_b[2] = { (const float*)d_in[3],  (const float*)d_in[12] };
    const float* W_x[2]    = { (const float*)d_in[4],  (const float*)d_in[13] };
    const float* W_dt[2]   = { (const float*)d_in[5],  (const float*)d_in[14] };
    const float* b_dt[2]   = { (const float*)d_in[6],  (const float*)d_in[15] };
    const float* A_log[2]  = { (const float*)d_in[7],  (const float*)d_in[16] };
    const float* Dvec[2]   = { (const float*)d_in[8],  (const float*)d_in[17] };
    const float* W_out[2]  = { (const float*)d_in[9],  (const float*)d_in[18] };
    float* out = (float*)d_out;

    float *p_xz, *p_xdbl, *p_xdblp, *p_dt;
    cudaGetSymbolAddress((void**)&p_xz,    g_xz);
    cudaGetSymbolAddress((void**)&p_xdbl,  g_xdbl);
    cudaGetSymbolAddress((void**)&p_xdblp, g_xdblp);
    cudaGetSymbolAddress((void**)&p_dt,    g_dt);
    bf16 *p_xh, *p_xl, *p_winh, *p_winl, *p_wouth, *p_woutl;
    bf16 *p_wxh, *p_wxl, *p_xch, *p_xcl, *p_yh, *p_yl;
    cudaGetSymbolAddress((void**)&p_xh,    g_x_h);
    cudaGetSymbolAddress((void**)&p_xl,    g_x_l);
    cudaGetSymbolAddress((void**)&p_winh,  g_win_h);
    cudaGetSymbolAddress((void**)&p_winl,  g_win_l);
    cudaGetSymbolAddress((void**)&p_wouth, g_wout_h);
    cudaGetSymbolAddress((void**)&p_woutl, g_wout_l);
    cudaGetSymbolAddress((void**)&p_wxh,   g_wx_h);
    cudaGetSymbolAddress((void**)&p_wxl,   g_wx_l);
    cudaGetSymbolAddress((void**)&p_xch,   g_xc_h);
    cudaGetSymbolAddress((void**)&p_xcl,   g_xc_l);
    cudaGetSymbolAddress((void**)&p_yh,    g_y_h);
    cudaGetSymbolAddress((void**)&p_yl,    g_y_l);

    const int M = BB * LL;  // 2048

    const int SMEM_G0 = 2 * (2 * 128 + 256) * 80;   // 81920
    const int SMEM_G1 = 2 * (2 * 64 + 256) * 80;    // 61440
    cudaFuncSetAttribute(mma_gemm<0,128>, cudaFuncAttributeMaxDynamicSharedMemorySize, SMEM_G0);
    cudaFuncSetAttribute(mma_gemm<1,64>,  cudaFuncAttributeMaxDynamicSharedMemorySize, SMEM_G1);
    cudaFuncSetAttribute(mma_gemm<2,64>,  cudaFuncAttributeMaxDynamicSharedMemorySize, SMEM_G1);

    // 0) hi/lo splits (one launch, 7 regions; W_x zero-padded to 128 rows)
    {
        SplitArgs a;
        a.src[0] = x;        a.hi[0] = p_xh;    a.lo[0] = p_xl;
        a.n4[0] = M * DIMM / 4;            a.srcN4[0] = a.n4[0];
        a.src[1] = W_in[0];  a.hi[1] = p_winh;  a.lo[1] = p_winl;
        a.n4[1] = 2 * DI * DIMM / 4;       a.srcN4[1] = a.n4[1];
        a.src[2] = W_in[1];  a.hi[2] = p_winh + (size_t)2*DI*DIMM;
                             a.lo[2] = p_winl + (size_t)2*DI*DIMM;
        a.n4[2] = 2 * DI * DIMM / 4;       a.srcN4[2] = a.n4[2];
        a.src[3] = W_out[0]; a.hi[3] = p_wouth; a.lo[3] = p_woutl;
        a.n4[3] = DIMM * DI / 4;           a.srcN4[3] = a.n4[3];
        a.src[4] = W_out[1]; a.hi[4] = p_wouth + (size_t)DIMM*DI;
                             a.lo[4] = p_woutl + (size_t)DIMM*DI;
        a.n4[4] = DIMM * DI / 4;           a.srcN4[4] = a.n4[4];
        a.src[5] = W_x[0];   a.hi[5] = p_wxh;   a.lo[5] = p_wxl;
        a.n4[5] = NXP * DI / 4;            a.srcN4[5] = NX * DI / 4;
        a.src[6] = W_x[1];   a.hi[6] = p_wxh + (size_t)NXP*DI;
                             a.lo[6] = p_wxl + (size_t)NXP*DI;
        a.n4[6] = NXP * DI / 4;            a.srcN4[6] = NX * DI / 4;
        int maxn4 = 2 * DI * DIMM / 4;
        dim3 grid(cdiv(maxn4, 256), 7);
        split_all_kernel<<<grid, 256>>>(a);
    }

    // 1) xz = x(+flip) @ W_in^T  (HMMA, 2-stage)
    {
        dim3 grid(2 * DI / 128, M / 128, 2);
        mma_gemm<0, 128><<<grid, 256, SMEM_G0>>>(
            p_xh, p_xl, p_winh, p_winl,
            p_xz, nullptr,
            DIMM, 2 * DI,
            0, (size_t)2*DI*DIMM, (size_t)M * 2 * DI);
    }

    // 2) conv + silu -> g_xc (fp32 + bf16 hi/lo)
    {
        int n4 = 2 * BB * LL * DI / 4;
        conv_silu_kernel<<<cdiv(n4, 256), 256>>>(conv_w[0], conv_b[0], conv_w[1], conv_b[1]);
    }

    // 3) x_dbl = xc @ W_x^T  (HMMA MODE 2, split-K2, partials + reduce)
    {
        dim3 grid(2, M / 64, 2);
        mma_gemm<2, 64><<<grid, 256, SMEM_G1>>>(
            p_xch, p_xcl, p_wxh, p_wxl,
            p_xdblp, nullptr,
            DI, NX,
            (size_t)M * DI, (size_t)NXP * DI, (size_t)M * NX);
        int n4 = 2 * M * NX / 4;
        xdbl_reduce_kernel<<<cdiv(n4, 256), 256>>>();
    }

    // 4) dt = softplus(x_dbl[:, :48] @ W_dt^T + b_dt)
    {
        dim3 grid(DI / 128, M / 128, 2);
        gemm_dt<128,128,16,8,8><<<grid, 256>>>(
            p_xdbl, NX, (size_t)M * NX,
            W_dt[0], W_dt[1],
            p_dt, DI, (size_t)M * DI,
            M, DI, DTR, b_dt[0], b_dt[1]);
    }

    // 5) selective scan + gating -> y hi/lo
    {
        dim3 grid(DI / 32, BB, 2);
        scan_kernel<<<grid, 256>>>(A_log[0], Dvec[0], A_log[1], Dvec[1]);
    }

    // 6) out = x + y0 @ W0^T + flip(y1) @ W1^T  (HMMA, 2-stage)
    {
        dim3 grid(DIMM / 128, M / 64, 1);
        mma_gemm<1, 64><<<grid, 256, SMEM_G1>>>(
            p_yh, p_yl, p_wouth, p_woutl,
            out, x,
            DI, DIMM,
            (size_t)M * DI, (size_t)DIMM * DI, 0);
    }

    (void)in_sizes; (void)n_in; (void)out_size;
}

// round 13
// speedup vs baseline: 1.3107x; 1.2563x over previous
#include <cuda_runtime.h>
#include <cuda_fp16.h>
#include <math.h>
#include <stdint.h>

#define BB   2
#define LL   1024
#define DIMM 768
#define DI   1536
#define DS   16
#define DTR  48
#define NX   80   // DTR + 2*DS
#define NXP  128  // padded N for xdbl HMMA
#define TT   64   // scan time tile

typedef __half fp16;

// ---------------- device scratch ----------------
__device__ float g_xz   [2 * BB * LL * 2 * DI];   // [dir][m][3072]
__device__ float g_xc   [2 * BB * LL * DI];
__device__ float g_xdbl [2 * BB * LL * NX];
__device__ float g_xdblp[2 * 2 * BB * LL * NX];   // [ksplit][dir][m][nx]
__device__ float g_dt   [2 * BB * LL * DI];

__device__ fp16 g_x_h  [BB * LL * DIMM];
__device__ fp16 g_x_l  [BB * LL * DIMM];
__device__ fp16 g_win  [2 * 2 * DI * DIMM];
__device__ fp16 g_wout [2 * DIMM * DI];
__device__ fp16 g_wx   [2 * NXP * DI];            // zero-padded rows 80..127
__device__ fp16 g_xc_h [2 * BB * LL * DI];
__device__ fp16 g_xc_l [2 * BB * LL * DI];
__device__ fp16 g_y_h  [2 * BB * LL * DI];
__device__ fp16 g_y_l  [2 * BB * LL * DI];

__device__ __forceinline__ int fliprow(int m) {
    return (m & ~1023) + (1023 - (m & 1023));
}

__device__ __forceinline__ uint32_t smem_u32(const void* p) {
    uint32_t a;
    asm("{ .reg .u64 t; cvta.to.shared.u64 t, %1; cvt.u32.u64 %0, t; }" : "=r"(a) : "l"(p));
    return a;
}

__device__ __forceinline__ void ldmx4(uint32_t* r, uint32_t addr) {
    asm volatile("ldmatrix.sync.aligned.m8n8.x4.shared.b16 {%0,%1,%2,%3}, [%4];"
        : "=r"(r[0]), "=r"(r[1]), "=r"(r[2]), "=r"(r[3]) : "r"(addr));
}

__device__ __forceinline__ void mma16816(float* d, const uint32_t* a, const uint32_t* b) {
    asm volatile("mma.sync.aligned.m16n8k16.row.col.f32.f16.f16.f32 "
        "{%0,%1,%2,%3}, {%4,%5,%6,%7}, {%8,%9}, {%0,%1,%2,%3};"
        : "+f"(d[0]), "+f"(d[1]), "+f"(d[2]), "+f"(d[3])
        : "r"(a[0]), "r"(a[1]), "r"(a[2]), "r"(a[3]), "r"(b[0]), "r"(b[1]));
}

__device__ __forceinline__ void cp_async16(uint32_t dst, const void* src) {
    asm volatile("cp.async.cg.shared.global [%0], [%1], 16;" :: "r"(dst), "l"(src));
}
__device__ __forceinline__ void cp_commit() {
    asm volatile("cp.async.commit_group;" ::: "memory");
}
template<int N>
__device__ __forceinline__ void cp_wait() {
    asm volatile("cp.async.wait_group %0;" :: "n"(N) : "memory");
}

// =======================================================================
// HMMA fp16 2-product GEMM: per chunk load Ah, Al, W; acc += Ah*W + Al*W.
// 2-stage cp.async ring. Pass-major mma ordering.
// MODE 0 (xz):   dir = blockIdx.z; A = x (flip if dir), C[dir]
// MODE 1 (wout): C = X + sum_dir A(y[dir], flip if dir) @ W[dir]^T
// MODE 2 (xdbl): dir = blockIdx.z; ksplit = blockIdx.x (n0=0);
//                partial C slab [ksplit*2+dir], store cols < NX only
// BN=128, BK=32, K%32==0.
// =======================================================================
template<int MODE, int BM>
__global__ void __launch_bounds__(256)
mma_gemm(const fp16* __restrict__ Ah, const fp16* __restrict__ Al,
         const fp16* __restrict__ W,
         float* __restrict__ C, const float* __restrict__ X,
         int K, int ldc, size_t aDirStride, size_t wDirStride, size_t cDirStride)
{
    constexpr int NWM = BM / 32;
    constexpr int NWN = 8 / NWM;
    constexpr int WNW = 128 / NWN;
    constexpr int NAT = WNW / 8;
    constexpr int AV  = BM * 4 / 256;     // vec16 per thread per A tile
    constexpr int ARS = 80;               // smem row stride (bytes)
    constexpr int T_AH = 0;
    constexpr int T_AL = BM * ARS;
    constexpr int T_W  = 2 * BM * ARS;
    constexpr int STAGE = (2 * BM + 128) * ARS;

    extern __shared__ __align__(128) unsigned char smem[];
    const uint32_t smem_u = smem_u32(smem);

    const int tid  = threadIdx.x;
    const int wid  = tid >> 5;
    const int lane = tid & 31;
    const int warp_m = wid % NWM;
    const int warp_n = wid / NWM;
    const int m0 = blockIdx.y * BM;
    const int n0 = (MODE == 2) ? 0 : blockIdx.x * 128;

    // ldmatrix per-lane offsets relative to tile base
    const int quad = lane >> 3, liq = lane & 7;
    const int khB = (quad >> 1) * 16;
    uint32_t aOff[2], bOff[NAT / 2];
#pragma unroll
    for (int ma = 0; ma < 2; ma++) {
        int r = warp_m * 32 + ma * 16 + (quad & 1) * 8 + liq;
        aOff[ma] = r * ARS + khB;
    }
#pragma unroll
    for (int p = 0; p < NAT / 2; p++) {
        int r = warp_n * WNW + p * 16 + (quad & 1) * 8 + liq;
        bOff[p] = r * ARS + khB;
    }

    // cp.async coords
    int a_row[AV], a_c16[AV];
#pragma unroll
    for (int i = 0; i < AV; i++) {
        int v = tid + i * 256;
        a_row[i] = v >> 2; a_c16[i] = v & 3;
    }
    int b_row[2], b_c16[2];
#pragma unroll
    for (int i = 0; i < 2; i++) {
        int v = tid + i * 256;
        b_row[i] = v >> 2; b_c16[i] = v & 3;
    }

    float acc[2][NAT][4];
#pragma unroll
    for (int ma = 0; ma < 2; ma++)
#pragma unroll
        for (int na = 0; na < NAT; na++)
#pragma unroll
            for (int j = 0; j < 4; j++) acc[ma][na][j] = 0.f;

    const int chunksPerK = (MODE == 2) ? (K / 64) : (K / 32);  // MODE2: half-K chain
    const int total = (MODE == 1) ? 2 * chunksPerK : chunksPerK;
    const int kbase = (MODE == 2) ? blockIdx.x * (K / 2) : 0;

    auto issue_stage = [&](int c, int s) {
        const int dir = (MODE == 1) ? (c / chunksPerK) : blockIdx.z;
        const int kc = kbase + (c % chunksPerK) * 32;
        const fp16* AhP = Ah + (size_t)dir * aDirStride;
        const fp16* AlP = Al + (size_t)dir * aDirStride;
        const fp16* WP  = W  + (size_t)dir * wDirStride;
        const bool flip = (MODE != 2) && (dir == 1);
        const uint32_t base = smem_u + s * STAGE;
#pragma unroll
        for (int i = 0; i < AV; i++) {
            int m = m0 + a_row[i];
            int row = flip ? fliprow(m) : m;
            size_t go = (size_t)row * K + kc + a_c16[i] * 8;
            uint32_t so = a_row[i] * ARS + a_c16[i] * 16;
            cp_async16(base + T_AH + so, AhP + go);
            cp_async16(base + T_AL + so, AlP + go);
        }
#pragma unroll
        for (int i = 0; i < 2; i++) {
            size_t go = (size_t)(n0 + b_row[i]) * K + kc + b_c16[i] * 8;
            uint32_t so = b_row[i] * ARS + b_c16[i] * 16;
            cp_async16(base + T_W + so, WP + go);
        }
        cp_commit();
    };

    issue_stage(0, 0);

    for (int c = 0; c < total; c++) {
        if (c + 1 < total) { issue_stage(c + 1, (c + 1) & 1); cp_wait<1>(); }
        else               { cp_wait<0>(); }
        __syncthreads();

        const uint32_t sbase = smem_u + (c & 1) * STAGE;
#pragma unroll
        for (int ks = 0; ks < 2; ks++) {
            const int ko = ks * 32;
            uint32_t ah[2][4], al[2][4];
            ldmx4(ah[0], sbase + T_AH + aOff[0] + ko);
            ldmx4(ah[1], sbase + T_AH + aOff[1] + ko);
            ldmx4(al[0], sbase + T_AL + aOff[0] + ko);
            ldmx4(al[1], sbase + T_AL + aOff[1] + ko);
            uint32_t bw[NAT][2];
#pragma unroll
            for (int p = 0; p < NAT / 2; p++) {
                uint32_t r[4];
                ldmx4(r, sbase + T_W + bOff[p] + ko);
                bw[2*p][0] = r[0]; bw[2*p][1] = r[2];
                bw[2*p+1][0] = r[1]; bw[2*p+1][1] = r[3];
            }
            // pass-major: all accumulators per product -> long RAW distance
#pragma unroll
            for (int ma = 0; ma < 2; ma++)
#pragma unroll
                for (int na = 0; na < NAT; na++)
                    mma16816(acc[ma][na], ah[ma], bw[na]);
#pragma unroll
            for (int ma = 0; ma < 2; ma++)
#pragma unroll
                for (int na = 0; na < NAT; na++)
                    mma16816(acc[ma][na], al[ma], bw[na]);
        }
        __syncthreads();
    }

    // epilogue
    float* Cd;
    if (MODE == 1)      Cd = C;
    else if (MODE == 2) Cd = C + (size_t)(blockIdx.x * 2 + blockIdx.z) * cDirStride;
    else                Cd = C + (size_t)blockIdx.z * cDirStride;
#pragma unroll
    for (int ma = 0; ma < 2; ma++) {
#pragma unroll
        for (int na = 0; na < NAT; na++) {
            int row = m0 + warp_m * 32 + ma * 16 + (lane >> 2);
            int col = n0 + warp_n * WNW + na * 8 + 2 * (lane & 3);
            if (MODE == 2 && col >= NX) continue;
            float2 v0 = make_float2(acc[ma][na][0], acc[ma][na][1]);
            float2 v1 = make_float2(acc[ma][na][2], acc[ma][na][3]);
            if (MODE == 1) {
                float2 x0 = *(const float2*)&X[(size_t)row * ldc + col];
                float2 x1 = *(const float2*)&X[(size_t)(row + 8) * ldc + col];
                v0.x += x0.x; v0.y += x0.y; v1.x += x1.x; v1.y += x1.y;
            }
            *(float2*)&Cd[(size_t)row * ldc + col] = v0;
            *(float2*)&Cd[(size_t)(row + 8) * ldc + col] = v1;
        }
    }
}

// ==================== xdbl partial reduce ====================
__global__ void xdbl_reduce_kernel()
{
    const int N4 = 2 * BB * LL * NX / 4;   // float4 count of one k-half
    int i = blockIdx.x * blockDim.x + threadIdx.x;
    if (i >= N4) return;
    const float4* P = (const float4*)g_xdblp;
    float4 a = P[i];
    float4 b = P[i + N4];
    a.x += b.x; a.y += b.y; a.z += b.z; a.w += b.w;
    ((float4*)g_xdbl)[i] = a;
}

// ==================== fused hi/lo split prep ====================
// lo[r] == nullptr -> single-precision region (weights).
struct SplitArgs {
    const float* src[7];
    fp16* hi[7];
    fp16* lo[7];
    int n4[7];
    int srcN4[7];
};

__global__ void split_all_kernel(SplitArgs a)
{
    const int r = blockIdx.y;
    int i = blockIdx.x * blockDim.x + threadIdx.x;
    if (i >= a.n4[r]) return;
    float4 v = (i < a.srcN4[r]) ? ((const float4*)a.src[r])[i]
                                : make_float4(0.f, 0.f, 0.f, 0.f);
    fp16 h0 = __float2half_rn(v.x), h1 = __float2half_rn(v.y);
    fp16 h2 = __float2half_rn(v.z), h3 = __float2half_rn(v.w);
    ((__half2*)a.hi[r])[2*i]   = __halves2half2(h0, h1);
    ((__half2*)a.hi[r])[2*i+1] = __halves2half2(h2, h3);
    if (a.lo[r]) {
        fp16 l0 = __float2half_rn(v.x - __half2float(h0));
        fp16 l1 = __float2half_rn(v.y - __half2float(h1));
        fp16 l2 = __float2half_rn(v.z - __half2float(h2));
        fp16 l3 = __float2half_rn(v.w - __half2float(h3));
        ((__half2*)a.lo[r])[2*i]   = __halves2half2(l0, l1);
        ((__half2*)a.lo[r])[2*i+1] = __halves2half2(l2, l3);
    }
}

// ==================== SIMT GEMM for dt (K=48) ====================
template<int BM, int BN, int BK, int TM, int TN>
__global__ void __launch_bounds__((BM/TM)*(BN/TN), 2)
gemm_dt(const float* __restrict__ A, int lda, size_t aStride,
        const float* __restrict__ W0, const float* __restrict__ W1,
        float* __restrict__ C, int ldc, size_t cStride,
        int M, int N, int K,
        const float* __restrict__ bias0, const float* __restrict__ bias1)
{
    constexpr int THREADS = (BM/TM)*(BN/TN);
    constexpr int AF4 = BM*BK/4/THREADS;
    constexpr int BF4 = BN*BK/4/THREADS;
    __shared__ float As[BK][BM+4];
    __shared__ float Bs[BK][BN+4];

    const int tid = threadIdx.x;
    const int tx  = tid % (BN/TN);
    const int ty  = tid / (BN/TN);
    const int m0  = blockIdx.y * BM;
    const int n0  = blockIdx.x * BN;
    const int dir = blockIdx.z;

    const float* Ab = A + (size_t)dir * aStride;
    const float* W  = dir ? W1 : W0;
    const float* bias = dir ? bias1 : bias0;
    float* Cb = C + (size_t)dir * cStride;

    int a_mm[AF4], a_kk[AF4]; const float* a_ptr[AF4];
#pragma unroll
    for (int i = 0; i < AF4; i++) {
        int idx = tid + i * THREADS;
        a_mm[i] = idx / (BK/4); a_kk[i] = (idx % (BK/4)) * 4;
        a_ptr[i] = Ab + (size_t)(m0 + a_mm[i]) * lda + a_kk[i];
    }
    int b_nn[BF4], b_kk[BF4]; const float* b_ptr[BF4];
#pragma unroll
    for (int i = 0; i < BF4; i++) {
        int idx = tid + i * THREADS;
        b_nn[i] = idx / (BK/4); b_kk[i] = (idx % (BK/4)) * 4;
        b_ptr[i] = W + (size_t)(n0 + b_nn[i]) * K + b_kk[i];
    }

    float acc[TM][TN];
#pragma unroll
    for (int i = 0; i < TM; i++)
#pragma unroll
        for (int j = 0; j < TN; j++) acc[i][j] = 0.f;

    for (int k0 = 0; k0 < K; k0 += BK) {
#pragma unroll
        for (int i = 0; i < AF4; i++) {
            float4 v = *(const float4*)(a_ptr[i] + k0);
            As[a_kk[i]+0][a_mm[i]] = v.x; As[a_kk[i]+1][a_mm[i]] = v.y;
            As[a_kk[i]+2][a_mm[i]] = v.z; As[a_kk[i]+3][a_mm[i]] = v.w;
        }
#pragma unroll
        for (int i = 0; i < BF4; i++) {
            float4 v = *(const float4*)(b_ptr[i] + k0);
            Bs[b_kk[i]+0][b_nn[i]] = v.x; Bs[b_kk[i]+1][b_nn[i]] = v.y;
            Bs[b_kk[i]+2][b_nn[i]] = v.z; Bs[b_kk[i]+3][b_nn[i]] = v.w;
        }
        __syncthreads();
#pragma unroll
        for (int kk = 0; kk < BK; kk++) {
            float a[TM], b[TN];
#pragma unroll
            for (int i = 0; i < TM; i += 4) {
                float4 v = *(const float4*)&As[kk][ty*TM + i];
                a[i] = v.x; a[i+1] = v.y; a[i+2] = v.z; a[i+3] = v.w;
            }
#pragma unroll
            for (int j = 0; j < TN; j += 4) {
                float4 v = *(const float4*)&Bs[kk][tx*TN + j];
                b[j] = v.x; b[j+1] = v.y; b[j+2] = v.z; b[j+3] = v.w;
            }
#pragma unroll
            for (int i = 0; i < TM; i++)
#pragma unroll
                for (int j = 0; j < TN; j++) acc[i][j] += a[i] * b[j];
        }
        __syncthreads();
    }

#pragma unroll
    for (int i = 0; i < TM; i++) {
        int m = m0 + ty*TM + i;
#pragma unroll
        for (int j = 0; j < TN; j += 4) {
            int n = n0 + tx*TN + j;
            float4 v = make_float4(acc[i][j], acc[i][j+1], acc[i][j+2], acc[i][j+3]);
            v.x += bias[n+0]; v.y += bias[n+1]; v.z += bias[n+2]; v.w += bias[n+3];
            v.x = (v.x > 20.f) ? v.x : log1pf(expf(v.x));
            v.y = (v.y > 20.f) ? v.y : log1pf(expf(v.y));
            v.z = (v.z > 20.f) ? v.z : log1pf(expf(v.z));
            v.w = (v.w > 20.f) ? v.w : log1pf(expf(v.w));
            *(float4*)&Cb[(size_t)m * ldc + n] = v;
        }
    }
}

// ==================== conv + silu (emits fp32 + fp16 hi/lo) ====================
__global__ void conv_silu_kernel(const float* __restrict__ cw_f, const float* __restrict__ cb_f,
                                 const float* __restrict__ cw_b, const float* __restrict__ cb_b)
{
    const int TOT4 = 2 * BB * LL * DI / 4;
    int idx = blockIdx.x * blockDim.x + threadIdx.x;
    if (idx >= TOT4) return;
    const int DQ = DI / 4;
    int dq = idx % DQ;
    int r = idx / DQ;
    int t = r % LL; r /= LL;
    int b = r % BB;
    int dir = r / BB;
    int d4 = dq * 4;
    const float* w  = dir ? cw_b : cw_f;
    const float* cb = dir ? cb_b : cb_f;
    const float* xp = g_xz + ((size_t)(dir * BB + b)) * LL * 2 * DI;

    float4 wr0 = *(const float4*)&w[(d4+0)*4];
    float4 wr1 = *(const float4*)&w[(d4+1)*4];
    float4 wr2 = *(const float4*)&w[(d4+2)*4];
    float4 wr3 = *(const float4*)&w[(d4+3)*4];
    float4 s = *(const float4*)&cb[d4];
#pragma unroll
    for (int k = 0; k < 4; k++) {
        int tt = t + k - 3;
        if (tt >= 0) {
            float4 xv = *(const float4*)&xp[(size_t)tt * 2 * DI + d4];
            s.x += ((const float*)&wr0)[k] * xv.x;
            s.y += ((const float*)&wr1)[k] * xv.y;
            s.z += ((const float*)&wr2)[k] * xv.z;
            s.w += ((const float*)&wr3)[k] * xv.w;
        }
    }
    s.x = s.x / (1.f + __expf(-s.x));
    s.y = s.y / (1.f + __expf(-s.y));
    s.z = s.z / (1.f + __expf(-s.z));
    s.w = s.w / (1.f + __expf(-s.w));
    ((float4*)g_xc)[idx] = s;

    fp16 h0 = __float2half_rn(s.x), h1 = __float2half_rn(s.y);
    fp16 h2 = __float2half_rn(s.z), h3 = __float2half_rn(s.w);
    ((__half2*)g_xc_h)[2*idx]   = __halves2half2(h0, h1);
    ((__half2*)g_xc_h)[2*idx+1] = __halves2half2(h2, h3);
    fp16 l0 = __float2half_rn(s.x - __half2float(h0));
    fp16 l1 = __float2half_rn(s.y - __half2float(h1));
    fp16 l2 = __float2half_rn(s.z - __half2float(h2));
    fp16 l3 = __float2half_rn(s.w - __half2float(h3));
    ((__half2*)g_xc_l)[2*idx]   = __halves2half2(l0, l1);
    ((__half2*)g_xc_l)[2*idx+1] = __halves2half2(l2, l3);
}

// ==================== selective scan (smem time-tiled) ====================
__global__ void __launch_bounds__(256)
scan_kernel(const float* __restrict__ Alog_f, const float* __restrict__ D_f,
            const float* __restrict__ Alog_b, const float* __restrict__ D_b)
{
    __shared__ float s_dt[TT][32], s_xc[TT][32], s_z[TT][32], s_bc[TT][32];
    __shared__ fp16  s_yh[TT][32], s_yl[TT][32];

    const int tid = threadIdx.x;
    const int s4 = tid & 7;
    const int dl = tid >> 3;
    const int d0  = blockIdx.x * 32;
    const int b   = blockIdx.y;
    const int dir = blockIdx.z;

    const float* Alog = dir ? Alog_b : Alog_f;
    const float* Dp   = dir ? D_b   : D_f;

    const size_t base_di = ((size_t)(dir * BB + b)) * LL * DI;
    const size_t base_x  = ((size_t)(dir * BB + b)) * LL * NX;
    const size_t base_z  = ((size_t)(dir * BB + b)) * LL * 2 * DI + DI;

    float2 Av = *(const float2*)&Alog[(d0 + dl) * DS + 2*s4];
    const float A0 = -__expf(Av.x);
    const float A1 = -__expf(Av.y);
    const float Dv = Dp[d0 + dl];

    float h0 = 0.f, h1 = 0.f;

    for (int t0 = 0; t0 < LL; t0 += TT) {
#pragma unroll
        for (int i = tid; i < TT * 32; i += 256) {
            int t = i >> 5, d = i & 31;
            size_t r = base_di + (size_t)(t0 + t) * DI + d0 + d;
            s_dt[t][d] = g_dt[r];
            s_xc[t][d] = g_xc[r];
            s_z [t][d] = g_xz[base_z + (size_t)(t0 + t) * 2 * DI + d0 + d];
            s_bc[t][d] = g_xdbl[base_x + (size_t)(t0 + t) * NX + DTR + d];
        }
        __syncthreads();

#pragma unroll 8
        for (int t = 0; t < TT; t++) {
            float dtv = s_dt[t][dl];
            float xcv = s_xc[t][dl];
            float B0 = s_bc[t][2*s4],      B1 = s_bc[t][2*s4 + 1];
            float C0 = s_bc[t][16 + 2*s4], C1 = s_bc[t][17 + 2*s4];
            float dx  = dtv * xcv;
            h0 = __expf(dtv * A0) * h0 + dx * B0;
            h1 = __expf(dtv * A1) * h1 + dx * B1;
            float p = h0 * C0 + h1 * C1;
            p += __shfl_xor_sync(0xffffffffu, p, 4);
            p += __shfl_xor_sync(0xffffffffu, p, 2);
            p += __shfl_xor_sync(0xffffffffu, p, 1);
            if (s4 == 0) {
                float zv = s_z[t][dl];
                float y = p + xcv * Dv;
                float sig = 1.f / (1.f + __expf(-zv));
                y = y * (zv * sig);
                fp16 h = __float2half_rn(y);
                s_yh[t][dl] = h;
                s_yl[t][dl] = __float2half_rn(y - __half2float(h));
            }
        }
        __syncthreads();

#pragma unroll
        for (int i = tid; i < TT * 32; i += 256) {
            int t = i >> 5, d = i & 31;
            size_t r = base_di + (size_t)(t0 + t) * DI + d0 + d;
            g_y_h[r] = s_yh[t][d];
            g_y_l[r] = s_yl[t][d];
        }
        __syncthreads();
    }
}

static inline int cdiv(int a, int b) { return (a + b - 1) / b; }

extern "C" void kernel_launch(void* const* d_in, const int* in_sizes, int n_in,
                              void* d_out, int out_size)
{
    const float* x = (const float*)d_in[0];
    const float* W_in[2]   = { (const float*)d_in[1],  (const float*)d_in[10] };
    const float* conv_w[2] = { (const float*)d_in[2],  (const float*)d_in[11] };
    const float* conv_b[2] = { (const float*)d_in[3],  (const float*)d_in[12] };
    const float* W_x[2]    = { (const float*)d_in[4],  (const float*)d_in[13] };
    const float* W_dt[2]   = { (const float*)d_in[5],  (const float*)d_in[14] };
    const float* b_dt[2]   = { (const float*)d_in[6],  (const float*)d_in[15] };
    const float* A_log[2]  = { (const float*)d_in[7],  (const float*)d_in[16] };
    const float* Dvec[2]   = { (const float*)d_in[8],  (const float*)d_in[17] };
    const float* W_out[2]  = { (const float*)d_in[9],  (const float*)d_in[18] };
    float* out = (float*)d_out;

    float *p_xz, *p_xdbl, *p_xdblp, *p_dt;
    cudaGetSymbolAddress((void**)&p_xz,    g_xz);
    cudaGetSymbolAddress((void**)&p_xdbl,  g_xdbl);
    cudaGetSymbolAddress((void**)&p_xdblp, g_xdblp);
    cudaGetSymbolAddress((void**)&p_dt,    g_dt);
    fp16 *p_xh, *p_xl, *p_win, *p_wout, *p_wx, *p_xch, *p_xcl, *p_yh, *p_yl;
    cudaGetSymbolAddress((void**)&p_xh,   g_x_h);
    cudaGetSymbolAddress((void**)&p_xl,   g_x_l);
    cudaGetSymbolAddress((void**)&p_win,  g_win);
    cudaGetSymbolAddress((void**)&p_wout, g_wout);
    cudaGetSymbolAddress((void**)&p_wx,   g_wx);
    cudaGetSymbolAddress((void**)&p_xch,  g_xc_h);
    cudaGetSymbolAddress((void**)&p_xcl,  g_xc_l);
    cudaGetSymbolAddress((void**)&p_yh,   g_y_h);
    cudaGetSymbolAddress((void**)&p_yl,   g_y_l);

    const int M = BB * LL;  // 2048

    const int SMEM_G0 = 2 * (2 * 128 + 128) * 80;   // 61440
    const int SMEM_G1 = 2 * (2 * 64 + 128) * 80;    // 40960
    cudaFuncSetAttribute(mma_gemm<0,128>, cudaFuncAttributeMaxDynamicSharedMemorySize, SMEM_G0);
    cudaFuncSetAttribute(mma_gemm<1,64>,  cudaFuncAttributeMaxDynamicSharedMemorySize, SMEM_G1);
    cudaFuncSetAttribute(mma_gemm<2,64>,  cudaFuncAttributeMaxDynamicSharedMemorySize, SMEM_G1);

    // 0) fp16 splits (one launch, 7 regions; A-side hi/lo, weights hi only)
    {
        SplitArgs a;
        a.src[0] = x;        a.hi[0] = p_xh;   a.lo[0] = p_xl;
        a.n4[0] = M * DIMM / 4;            a.srcN4[0] = a.n4[0];
        a.src[1] = W_in[0];  a.hi[1] = p_win;  a.lo[1] = nullptr;
        a.n4[1] = 2 * DI * DIMM / 4;       a.srcN4[1] = a.n4[1];
        a.src[2] = W_in[1];  a.hi[2] = p_win + (size_t)2*DI*DIMM; a.lo[2] = nullptr;
        a.n4[2] = 2 * DI * DIMM / 4;       a.srcN4[2] = a.n4[2];
        a.src[3] = W_out[0]; a.hi[3] = p_wout; a.lo[3] = nullptr;
        a.n4[3] = DIMM * DI / 4;           a.srcN4[3] = a.n4[3];
        a.src[4] = W_out[1]; a.hi[4] = p_wout + (size_t)DIMM*DI; a.lo[4] = nullptr;
        a.n4[4] = DIMM * DI / 4;           a.srcN4[4] = a.n4[4];
        a.src[5] = W_x[0];   a.hi[5] = p_wx;   a.lo[5] = nullptr;
        a.n4[5] = NXP * DI / 4;            a.srcN4[5] = NX * DI / 4;
        a.src[6] = W_x[1];   a.hi[6] = p_wx + (size_t)NXP*DI; a.lo[6] = nullptr;
        a.n4[6] = NXP * DI / 4;            a.srcN4[6] = NX * DI / 4;
        int maxn4 = 2 * DI * DIMM / 4;
        dim3 grid(cdiv(maxn4, 256), 7);
        split_all_kernel<<<grid, 256>>>(a);
    }

    // 1) xz = x(+flip) @ W_in^T  (fp16 HMMA, 2-product)
    {
        dim3 grid(2 * DI / 128, M / 128, 2);
        mma_gemm<0, 128><<<grid, 256, SMEM_G0>>>(
            p_xh, p_xl, p_win,
            p_xz, nullptr,
            DIMM, 2 * DI,
            0, (size_t)2*DI*DIMM, (size_t)M * 2 * DI);
    }

    // 2) conv + silu -> g_xc (fp32 + fp16 hi/lo)
    {
        int n4 = 2 * BB * LL * DI / 4;
        conv_silu_kernel<<<cdiv(n4, 256), 256>>>(conv_w[0], conv_b[0], conv_w[1], conv_b[1]);
    }

    // 3) x_dbl = xc @ W_x^T  (fp16 HMMA MODE 2, split-K2, partials + reduce)
    {
        dim3 grid(2, M / 64, 2);
        mma_gemm<2, 64><<<grid, 256, SMEM_G1>>>(
            p_xch, p_xcl, p_wx,
            p_xdblp, nullptr,
            DI, NX,
            (size_t)M * DI, (size_t)NXP * DI, (size_t)M * NX);
        int n4 = 2 * M * NX / 4;
        xdbl_reduce_kernel<<<cdiv(n4, 256), 256>>>();
    }

    // 4) dt = softplus(x_dbl[:, :48] @ W_dt^T + b_dt)
    {
        dim3 grid(DI / 128, M / 128, 2);
        gemm_dt<128,128,16,8,8><<<grid, 256>>>(
            p_xdbl, NX, (size_t)M * NX,
            W_dt[0], W_dt[1],
            p_dt, DI, (size_t)M * DI,
            M, DI, DTR, b_dt[0], b_dt[1]);
    }

    // 5) selective scan + gating -> y hi/lo (fp16)
    {
        dim3 grid(DI / 32, BB, 2);
        scan_kernel<<<grid, 256>>>(A_log[0], Dvec[0], A_log[1], Dvec[1]);
    }

    // 6) out = x + y0 @ W0^T + flip(y1) @ W1^T  (fp16 HMMA, 2-product)
    {
        dim3 grid(DIMM / 128, M / 64, 1);
        mma_gemm<1, 64><<<grid, 256, SMEM_G1>>>(
            p_yh, p_yl, p_wout,
            out, x,
            DI, DIMM,
            (size_t)M * DI, (size_t)DIMM * DI, 0);
    }

    (void)in_sizes; (void)n_in; (void)out_size;
}

// round 14
// speedup vs baseline: 1.7303x; 1.3202x over previous
#include <cuda_runtime.h>
#include <cuda_fp16.h>
#include <math.h>
#include <stdint.h>

#define BB   2
#define LL   1024
#define DIMM 768
#define DI   1536
#define DS   16
#define DTR  48
#define NX   80   // DTR + 2*DS
#define NXP  128  // padded N for xdbl HMMA
#define TT   64   // scan time tile

typedef __half fp16;

// ---------------- device scratch ----------------
__device__ float g_xz   [2 * BB * LL * 2 * DI];   // [dir][m][3072]
__device__ float g_xc   [2 * BB * LL * DI];
__device__ float g_xdbl [2 * BB * LL * NX];
__device__ float g_xdblp[2 * 2 * BB * LL * NX];   // [ksplit][dir][m][nx]
__device__ float g_dt   [2 * BB * LL * DI];

__device__ fp16 g_x_f  [BB * LL * DIMM];
__device__ fp16 g_win  [2 * 2 * DI * DIMM];
__device__ fp16 g_wout [2 * DIMM * DI];
__device__ fp16 g_wx   [2 * NXP * DI];            // zero-padded rows 80..127
__device__ fp16 g_xc_f [2 * BB * LL * DI];
__device__ fp16 g_y_f  [2 * BB * LL * DI];

__device__ __forceinline__ int fliprow(int m) {
    return (m & ~1023) + (1023 - (m & 1023));
}

__device__ __forceinline__ uint32_t smem_u32(const void* p) {
    uint32_t a;
    asm("{ .reg .u64 t; cvta.to.shared.u64 t, %1; cvt.u32.u64 %0, t; }" : "=r"(a) : "l"(p));
    return a;
}

__device__ __forceinline__ void ldmx4(uint32_t* r, uint32_t addr) {
    asm volatile("ldmatrix.sync.aligned.m8n8.x4.shared.b16 {%0,%1,%2,%3}, [%4];"
        : "=r"(r[0]), "=r"(r[1]), "=r"(r[2]), "=r"(r[3]) : "r"(addr));
}

__device__ __forceinline__ void mma16816(float* d, const uint32_t* a, const uint32_t* b) {
    asm volatile("mma.sync.aligned.m16n8k16.row.col.f32.f16.f16.f32 "
        "{%0,%1,%2,%3}, {%4,%5,%6,%7}, {%8,%9}, {%0,%1,%2,%3};"
        : "+f"(d[0]), "+f"(d[1]), "+f"(d[2]), "+f"(d[3])
        : "r"(a[0]), "r"(a[1]), "r"(a[2]), "r"(a[3]), "r"(b[0]), "r"(b[1]));
}

__device__ __forceinline__ void cp_async16(uint32_t dst, const void* src) {
    asm volatile("cp.async.cg.shared.global [%0], [%1], 16;" :: "r"(dst), "l"(src));
}
__device__ __forceinline__ void cp_commit() {
    asm volatile("cp.async.commit_group;" ::: "memory");
}
template<int N>
__device__ __forceinline__ void cp_wait() {
    asm volatile("cp.async.wait_group %0;" :: "n"(N) : "memory");
}

// =======================================================================
// HMMA fp16 single-product GEMM, BK=64 chunks, 2-stage cp.async ring.
// MODE 0 (xz):   dir = blockIdx.z; A = x (flip if dir), C[dir]
// MODE 1 (wout): C = X + sum_dir A(y[dir], flip if dir) @ W[dir]^T
// MODE 2 (xdbl): dir = blockIdx.z; ksplit = blockIdx.x (n0=0);
//                partial C slab [ksplit*2+dir], store cols < NX only
// BN=128. K%64==0 (MODE2: (K/2)%64==0).
// =======================================================================
template<int MODE, int BM>
__global__ void __launch_bounds__(256)
mma_gemm(const fp16* __restrict__ A, const fp16* __restrict__ W,
         float* __restrict__ C, const float* __restrict__ X,
         int K, int ldc, size_t aDirStride, size_t wDirStride, size_t cDirStride)
{
    constexpr int NWM = BM / 32;
    constexpr int NWN = 8 / NWM;
    constexpr int WNW = 128 / NWN;
    constexpr int NAT = WNW / 8;
    constexpr int AV  = BM * 8 / 256;     // vec16 per thread for A tile (row=128B)
    constexpr int ARS = 144;              // smem row stride (bytes): 128 data + 16 pad
    constexpr int T_A = 0;
    constexpr int T_W = BM * ARS;
    constexpr int STAGE = (BM + 128) * ARS;

    extern __shared__ __align__(128) unsigned char smem[];
    const uint32_t smem_u = smem_u32(smem);

    const int tid  = threadIdx.x;
    const int wid  = tid >> 5;
    const int lane = tid & 31;
    const int warp_m = wid % NWM;
    const int warp_n = wid / NWM;
    const int m0 = blockIdx.y * BM;
    const int n0 = (MODE == 2) ? 0 : blockIdx.x * 128;

    // ldmatrix per-lane offsets relative to tile base
    const int quad = lane >> 3, liq = lane & 7;
    const int khB = (quad >> 1) * 16;
    uint32_t aOff[2], bOff[NAT / 2];
#pragma unroll
    for (int ma = 0; ma < 2; ma++) {
        int r = warp_m * 32 + ma * 16 + (quad & 1) * 8 + liq;
        aOff[ma] = r * ARS + khB;
    }
#pragma unroll
    for (int p = 0; p < NAT / 2; p++) {
        int r = warp_n * WNW + p * 16 + (quad & 1) * 8 + liq;
        bOff[p] = r * ARS + khB;
    }

    // cp.async coords (8 vec16 per 128B row)
    int a_row[AV], a_c16[AV];
#pragma unroll
    for (int i = 0; i < AV; i++) {
        int v = tid + i * 256;
        a_row[i] = v >> 3; a_c16[i] = v & 7;
    }
    int b_row[4], b_c16[4];
#pragma unroll
    for (int i = 0; i < 4; i++) {
        int v = tid + i * 256;
        b_row[i] = v >> 3; b_c16[i] = v & 7;
    }

    float acc[2][NAT][4];
#pragma unroll
    for (int ma = 0; ma < 2; ma++)
#pragma unroll
        for (int na = 0; na < NAT; na++)
#pragma unroll
            for (int j = 0; j < 4; j++) acc[ma][na][j] = 0.f;

    const int chunksPerK = (MODE == 2) ? (K / 128) : (K / 64);  // MODE2: half-K chain
    const int total = (MODE == 1) ? 2 * chunksPerK : chunksPerK;
    const int kbase = (MODE == 2) ? blockIdx.x * (K / 2) : 0;

    auto issue_stage = [&](int c, int s) {
        const int dir = (MODE == 1) ? (c / chunksPerK) : blockIdx.z;
        const int kc = kbase + (c % chunksPerK) * 64;
        const fp16* AP = A + (size_t)dir * aDirStride;
        const fp16* WP = W + (size_t)dir * wDirStride;
        const bool flip = (MODE != 2) && (dir == 1);
        const uint32_t base = smem_u + s * STAGE;
#pragma unroll
        for (int i = 0; i < AV; i++) {
            int m = m0 + a_row[i];
            int row = flip ? fliprow(m) : m;
            cp_async16(base + T_A + a_row[i] * ARS + a_c16[i] * 16,
                       AP + (size_t)row * K + kc + a_c16[i] * 8);
        }
#pragma unroll
        for (int i = 0; i < 4; i++) {
            cp_async16(base + T_W + b_row[i] * ARS + b_c16[i] * 16,
                       WP + (size_t)(n0 + b_row[i]) * K + kc + b_c16[i] * 8);
        }
        cp_commit();
    };

    issue_stage(0, 0);

    for (int c = 0; c < total; c++) {
        if (c + 1 < total) { issue_stage(c + 1, (c + 1) & 1); cp_wait<1>(); }
        else               { cp_wait<0>(); }
        __syncthreads();

        const uint32_t sbase = smem_u + (c & 1) * STAGE;
#pragma unroll
        for (int ks = 0; ks < 4; ks++) {
            const int ko = ks * 32;
            uint32_t a[2][4];
            ldmx4(a[0], sbase + T_A + aOff[0] + ko);
            ldmx4(a[1], sbase + T_A + aOff[1] + ko);
            uint32_t bw[NAT][2];
#pragma unroll
            for (int p = 0; p < NAT / 2; p++) {
                uint32_t r[4];
                ldmx4(r, sbase + T_W + bOff[p] + ko);
                bw[2*p][0] = r[0]; bw[2*p][1] = r[2];
                bw[2*p+1][0] = r[1]; bw[2*p+1][1] = r[3];
            }
#pragma unroll
            for (int ma = 0; ma < 2; ma++)
#pragma unroll
                for (int na = 0; na < NAT; na++)
                    mma16816(acc[ma][na], a[ma], bw[na]);
        }
        __syncthreads();
    }

    // epilogue
    float* Cd;
    if (MODE == 1)      Cd = C;
    else if (MODE == 2) Cd = C + (size_t)(blockIdx.x * 2 + blockIdx.z) * cDirStride;
    else                Cd = C + (size_t)blockIdx.z * cDirStride;
#pragma unroll
    for (int ma = 0; ma < 2; ma++) {
#pragma unroll
        for (int na = 0; na < NAT; na++) {
            int row = m0 + warp_m * 32 + ma * 16 + (lane >> 2);
            int col = n0 + warp_n * WNW + na * 8 + 2 * (lane & 3);
            if (MODE == 2 && col >= NX) continue;
            float2 v0 = make_float2(acc[ma][na][0], acc[ma][na][1]);
            float2 v1 = make_float2(acc[ma][na][2], acc[ma][na][3]);
            if (MODE == 1) {
                float2 x0 = *(const float2*)&X[(size_t)row * ldc + col];
                float2 x1 = *(const float2*)&X[(size_t)(row + 8) * ldc + col];
                v0.x += x0.x; v0.y += x0.y; v1.x += x1.x; v1.y += x1.y;
            }
            *(float2*)&Cd[(size_t)row * ldc + col] = v0;
            *(float2*)&Cd[(size_t)(row + 8) * ldc + col] = v1;
        }
    }
}

// ==================== xdbl partial reduce ====================
__global__ void xdbl_reduce_kernel()
{
    const int N4 = 2 * BB * LL * NX / 4;   // float4 count of one k-half
    int i = blockIdx.x * blockDim.x + threadIdx.x;
    if (i >= N4) return;
    const float4* P = (const float4*)g_xdblp;
    float4 a = P[i];
    float4 b = P[i + N4];
    a.x += b.x; a.y += b.y; a.z += b.z; a.w += b.w;
    ((float4*)g_xdbl)[i] = a;
}

// ==================== fused fp16 convert prep ====================
struct SplitArgs {
    const float* src[7];
    fp16* dst[7];
    int n4[7];
    int srcN4[7];
};

__global__ void split_all_kernel(SplitArgs a)
{
    const int r = blockIdx.y;
    int i = blockIdx.x * blockDim.x + threadIdx.x;
    if (i >= a.n4[r]) return;
    float4 v = (i < a.srcN4[r]) ? ((const float4*)a.src[r])[i]
                                : make_float4(0.f, 0.f, 0.f, 0.f);
    fp16 h0 = __float2half_rn(v.x), h1 = __float2half_rn(v.y);
    fp16 h2 = __float2half_rn(v.z), h3 = __float2half_rn(v.w);
    ((__half2*)a.dst[r])[2*i]   = __halves2half2(h0, h1);
    ((__half2*)a.dst[r])[2*i+1] = __halves2half2(h2, h3);
}

// ==================== SIMT GEMM for dt (K=48) ====================
template<int BM, int BN, int BK, int TM, int TN>
__global__ void __launch_bounds__((BM/TM)*(BN/TN), 2)
gemm_dt(const float* __restrict__ A, int lda, size_t aStride,
        const float* __restrict__ W0, const float* __restrict__ W1,
        float* __restrict__ C, int ldc, size_t cStride,
        int M, int N, int K,
        const float* __restrict__ bias0, const float* __restrict__ bias1)
{
    constexpr int THREADS = (BM/TM)*(BN/TN);
    constexpr int AF4 = BM*BK/4/THREADS;
    constexpr int BF4 = BN*BK/4/THREADS;
    __shared__ float As[BK][BM+4];
    __shared__ float Bs[BK][BN+4];

    const int tid = threadIdx.x;
    const int tx  = tid % (BN/TN);
    const int ty  = tid / (BN/TN);
    const int m0  = blockIdx.y * BM;
    const int n0  = blockIdx.x * BN;
    const int dir = blockIdx.z;

    const float* Ab = A + (size_t)dir * aStride;
    const float* W  = dir ? W1 : W0;
    const float* bias = dir ? bias1 : bias0;
    float* Cb = C + (size_t)dir * cStride;

    int a_mm[AF4], a_kk[AF4]; const float* a_ptr[AF4];
#pragma unroll
    for (int i = 0; i < AF4; i++) {
        int idx = tid + i * THREADS;
        a_mm[i] = idx / (BK/4); a_kk[i] = (idx % (BK/4)) * 4;
        a_ptr[i] = Ab + (size_t)(m0 + a_mm[i]) * lda + a_kk[i];
    }
    int b_nn[BF4], b_kk[BF4]; const float* b_ptr[BF4];
#pragma unroll
    for (int i = 0; i < BF4; i++) {
        int idx = tid + i * THREADS;
        b_nn[i] = idx / (BK/4); b_kk[i] = (idx % (BK/4)) * 4;
        b_ptr[i] = W + (size_t)(n0 + b_nn[i]) * K + b_kk[i];
    }

    float acc[TM][TN];
#pragma unroll
    for (int i = 0; i < TM; i++)
#pragma unroll
        for (int j = 0; j < TN; j++) acc[i][j] = 0.f;

    for (int k0 = 0; k0 < K; k0 += BK) {
#pragma unroll
        for (int i = 0; i < AF4; i++) {
            float4 v = *(const float4*)(a_ptr[i] + k0);
            As[a_kk[i]+0][a_mm[i]] = v.x; As[a_kk[i]+1][a_mm[i]] = v.y;
            As[a_kk[i]+2][a_mm[i]] = v.z; As[a_kk[i]+3][a_mm[i]] = v.w;
        }
#pragma unroll
        for (int i = 0; i < BF4; i++) {
            float4 v = *(const float4*)(b_ptr[i] + k0);
            Bs[b_kk[i]+0][b_nn[i]] = v.x; Bs[b_kk[i]+1][b_nn[i]] = v.y;
            Bs[b_kk[i]+2][b_nn[i]] = v.z; Bs[b_kk[i]+3][b_nn[i]] = v.w;
        }
        __syncthreads();
#pragma unroll
        for (int kk = 0; kk < BK; kk++) {
            float a[TM], b[TN];
#pragma unroll
            for (int i = 0; i < TM; i += 4) {
                float4 v = *(const float4*)&As[kk][ty*TM + i];
                a[i] = v.x; a[i+1] = v.y; a[i+2] = v.z; a[i+3] = v.w;
            }
#pragma unroll
            for (int j = 0; j < TN; j += 4) {
                float4 v = *(const float4*)&Bs[kk][tx*TN + j];
                b[j] = v.x; b[j+1] = v.y; b[j+2] = v.z; b[j+3] = v.w;
            }
#pragma unroll
            for (int i = 0; i < TM; i++)
#pragma unroll
                for (int j = 0; j < TN; j++) acc[i][j] += a[i] * b[j];
        }
        __syncthreads();
    }

#pragma unroll
    for (int i = 0; i < TM; i++) {
        int m = m0 + ty*TM + i;
#pragma unroll
        for (int j = 0; j < TN; j += 4) {
            int n = n0 + tx*TN + j;
            float4 v = make_float4(acc[i][j], acc[i][j+1], acc[i][j+2], acc[i][j+3]);
            v.x += bias[n+0]; v.y += bias[n+1]; v.z += bias[n+2]; v.w += bias[n+3];
            v.x = (v.x > 20.f) ? v.x : log1pf(expf(v.x));
            v.y = (v.y > 20.f) ? v.y : log1pf(expf(v.y));
            v.z = (v.z > 20.f) ? v.z : log1pf(expf(v.z));
            v.w = (v.w > 20.f) ? v.w : log1pf(expf(v.w));
            *(float4*)&Cb[(size_t)m * ldc + n] = v;
        }
    }
}

// ==================== conv + silu (emits fp32 + fp16) ====================
__global__ void conv_silu_kernel(const float* __restrict__ cw_f, const float* __restrict__ cb_f,
                                 const float* __restrict__ cw_b, const float* __restrict__ cb_b)
{
    const int TOT4 = 2 * BB * LL * DI / 4;
    int idx = blockIdx.x * blockDim.x + threadIdx.x;
    if (idx >= TOT4) return;
    const int DQ = DI / 4;
    int dq = idx % DQ;
    int r = idx / DQ;
    int t = r % LL; r /= LL;
    int b = r % BB;
    int dir = r / BB;
    int d4 = dq * 4;
    const float* w  = dir ? cw_b : cw_f;
    const float* cb = dir ? cb_b : cb_f;
    const float* xp = g_xz + ((size_t)(dir * BB + b)) * LL * 2 * DI;

    float4 wr0 = *(const float4*)&w[(d4+0)*4];
    float4 wr1 = *(const float4*)&w[(d4+1)*4];
    float4 wr2 = *(const float4*)&w[(d4+2)*4];
    float4 wr3 = *(const float4*)&w[(d4+3)*4];
    float4 s = *(const float4*)&cb[d4];
#pragma unroll
    for (int k = 0; k < 4; k++) {
        int tt = t + k - 3;
        if (tt >= 0) {
            float4 xv = *(const float4*)&xp[(size_t)tt * 2 * DI + d4];
            s.x += ((const float*)&wr0)[k] * xv.x;
            s.y += ((const float*)&wr1)[k] * xv.y;
            s.z += ((const float*)&wr2)[k] * xv.z;
            s.w += ((const float*)&wr3)[k] * xv.w;
        }
    }
    s.x = s.x / (1.f + __expf(-s.x));
    s.y = s.y / (1.f + __expf(-s.y));
    s.z = s.z / (1.f + __expf(-s.z));
    s.w = s.w / (1.f + __expf(-s.w));
    ((float4*)g_xc)[idx] = s;

    fp16 h0 = __float2half_rn(s.x), h1 = __float2half_rn(s.y);
    fp16 h2 = __float2half_rn(s.z), h3 = __float2half_rn(s.w);
    ((__half2*)g_xc_f)[2*idx]   = __halves2half2(h0, h1);
    ((__half2*)g_xc_f)[2*idx+1] = __halves2half2(h2, h3);
}

// ==================== selective scan (smem time-tiled) ====================
__global__ void __launch_bounds__(256)
scan_kernel(const float* __restrict__ Alog_f, const float* __restrict__ D_f,
            const float* __restrict__ Alog_b, const float* __restrict__ D_b)
{
    __shared__ float s_dt[TT][32], s_xc[TT][32], s_z[TT][32], s_bc[TT][32];
    __shared__ fp16  s_y[TT][32];

    const int tid = threadIdx.x;
    const int s4 = tid & 7;
    const int dl = tid >> 3;
    const int d0  = blockIdx.x * 32;
    const int b   = blockIdx.y;
    const int dir = blockIdx.z;

    const float* Alog = dir ? Alog_b : Alog_f;
    const float* Dp   = dir ? D_b   : D_f;

    const size_t base_di = ((size_t)(dir * BB + b)) * LL * DI;
    const size_t base_x  = ((size_t)(dir * BB + b)) * LL * NX;
    const size_t base_z  = ((size_t)(dir * BB + b)) * LL * 2 * DI + DI;

    float2 Av = *(const float2*)&Alog[(d0 + dl) * DS + 2*s4];
    const float A0 = -__expf(Av.x);
    const float A1 = -__expf(Av.y);
    const float Dv = Dp[d0 + dl];

    float h0 = 0.f, h1 = 0.f;

    for (int t0 = 0; t0 < LL; t0 += TT) {
#pragma unroll
        for (int i = tid; i < TT * 32; i += 256) {
            int t = i >> 5, d = i & 31;
            size_t r = base_di + (size_t)(t0 + t) * DI + d0 + d;
            s_dt[t][d] = g_dt[r];
            s_xc[t][d] = g_xc[r];
            s_z [t][d] = g_xz[base_z + (size_t)(t0 + t) * 2 * DI + d0 + d];
            s_bc[t][d] = g_xdbl[base_x + (size_t)(t0 + t) * NX + DTR + d];
        }
        __syncthreads();

#pragma unroll 8
        for (int t = 0; t < TT; t++) {
            float dtv = s_dt[t][dl];
            float xcv = s_xc[t][dl];
            float B0 = s_bc[t][2*s4],      B1 = s_bc[t][2*s4 + 1];
            float C0 = s_bc[t][16 + 2*s4], C1 = s_bc[t][17 + 2*s4];
            float dx  = dtv * xcv;
            h0 = __expf(dtv * A0) * h0 + dx * B0;
            h1 = __expf(dtv * A1) * h1 + dx * B1;
            float p = h0 * C0 + h1 * C1;
            p += __shfl_xor_sync(0xffffffffu, p, 4);
            p += __shfl_xor_sync(0xffffffffu, p, 2);
            p += __shfl_xor_sync(0xffffffffu, p, 1);
            if (s4 == 0) {
                float zv = s_z[t][dl];
                float y = p + xcv * Dv;
                float sig = 1.f / (1.f + __expf(-zv));
                y = y * (zv * sig);
                s_y[t][dl] = __float2half_rn(y);
            }
        }
        __syncthreads();

#pragma unroll
        for (int i = tid; i < TT * 32; i += 256) {
            int t = i >> 5, d = i & 31;
            g_y_f[base_di + (size_t)(t0 + t) * DI + d0 + d] = s_y[t][d];
        }
        __syncthreads();
    }
}

static inline int cdiv(int a, int b) { return (a + b - 1) / b; }

extern "C" void kernel_launch(void* const* d_in, const int* in_sizes, int n_in,
                              void* d_out, int out_size)
{
    const float* x = (const float*)d_in[0];
    const float* W_in[2]   = { (const float*)d_in[1],  (const float*)d_in[10] };
    const float* conv_w[2] = { (const float*)d_in[2],  (const float*)d_in[11] };
    const float* conv_b[2] = { (const float*)d_in[3],  (const float*)d_in[12] };
    const float* W_x[2]    = { (const float*)d_in[4],  (const float*)d_in[13] };
    const float* W_dt[2]   = { (const float*)d_in[5],  (const float*)d_in[14] };
    const float* b_dt[2]   = { (const float*)d_in[6],  (const float*)d_in[15] };
    const float* A_log[2]  = { (const float*)d_in[7],  (const float*)d_in[16] };
    const float* Dvec[2]   = { (const float*)d_in[8],  (const float*)d_in[17] };
    const float* W_out[2]  = { (const float*)d_in[9],  (const float*)d_in[18] };
    float* out = (float*)d_out;

    float *p_xz, *p_xdbl, *p_xdblp, *p_dt;
    cudaGetSymbolAddress((void**)&p_xz,    g_xz);
    cudaGetSymbolAddress((void**)&p_xdbl,  g_xdbl);
    cudaGetSymbolAddress((void**)&p_xdblp, g_xdblp);
    cudaGetSymbolAddress((void**)&p_dt,    g_dt);
    fp16 *p_xf, *p_win, *p_wout, *p_wx, *p_xcf, *p_yf;
    cudaGetSymbolAddress((void**)&p_xf,   g_x_f);
    cudaGetSymbolAddress((void**)&p_win,  g_win);
    cudaGetSymbolAddress((void**)&p_wout, g_wout);
    cudaGetSymbolAddress((void**)&p_wx,   g_wx);
    cudaGetSymbolAddress((void**)&p_xcf,  g_xc_f);
    cudaGetSymbolAddress((void**)&p_yf,   g_y_f);

    const int M = BB * LL;  // 2048

    const int SMEM_G0 = 2 * (128 + 128) * 144;   // 73728
    const int SMEM_G1 = 2 * (64 + 128) * 144;    // 55296
    cudaFuncSetAttribute(mma_gemm<0,128>, cudaFuncAttributeMaxDynamicSharedMemorySize, SMEM_G0);
    cudaFuncSetAttribute(mma_gemm<1,64>,  cudaFuncAttributeMaxDynamicSharedMemorySize, SMEM_G1);
    cudaFuncSetAttribute(mma_gemm<2,64>,  cudaFuncAttributeMaxDynamicSharedMemorySize, SMEM_G1);

    // 0) fp16 converts (one launch, 7 regions)
    {
        SplitArgs a;
        a.src[0] = x;        a.dst[0] = p_xf;
        a.n4[0] = M * DIMM / 4;            a.srcN4[0] = a.n4[0];
        a.src[1] = W_in[0];  a.dst[1] = p_win;
        a.n4[1] = 2 * DI * DIMM / 4;       a.srcN4[1] = a.n4[1];
        a.src[2] = W_in[1];  a.dst[2] = p_win + (size_t)2*DI*DIMM;
        a.n4[2] = 2 * DI * DIMM / 4;       a.srcN4[2] = a.n4[2];
        a.src[3] = W_out[0]; a.dst[3] = p_wout;
        a.n4[3] = DIMM * DI / 4;           a.srcN4[3] = a.n4[3];
        a.src[4] = W_out[1]; a.dst[4] = p_wout + (size_t)DIMM*DI;
        a.n4[4] = DIMM * DI / 4;           a.srcN4[4] = a.n4[4];
        a.src[5] = W_x[0];   a.dst[5] = p_wx;
        a.n4[5] = NXP * DI / 4;            a.srcN4[5] = NX * DI / 4;
        a.src[6] = W_x[1];   a.dst[6] = p_wx + (size_t)NXP*DI;
        a.n4[6] = NXP * DI / 4;            a.srcN4[6] = NX * DI / 4;
        int maxn4 = 2 * DI * DIMM / 4;
        dim3 grid(cdiv(maxn4, 256), 7);
        split_all_kernel<<<grid, 256>>>(a);
    }

    // 1) xz = x(+flip) @ W_in^T  (fp16 HMMA single-product, BK=64)
    {
        dim3 grid(2 * DI / 128, M / 128, 2);
        mma_gemm<0, 128><<<grid, 256, SMEM_G0>>>(
            p_xf, p_win,
            p_xz, nullptr,
            DIMM, 2 * DI,
            0, (size_t)2*DI*DIMM, (size_t)M * 2 * DI);
    }

    // 2) conv + silu -> g_xc (fp32 + fp16)
    {
        int n4 = 2 * BB * LL * DI / 4;
        conv_silu_kernel<<<cdiv(n4, 256), 256>>>(conv_w[0], conv_b[0], conv_w[1], conv_b[1]);
    }

    // 3) x_dbl = xc @ W_x^T  (fp16 HMMA MODE 2, split-K2, partials + reduce)
    {
        dim3 grid(2, M / 64, 2);
        mma_gemm<2, 64><<<grid, 256, SMEM_G1>>>(
            p_xcf, p_wx,
            p_xdblp, nullptr,
            DI, NX,
            (size_t)M * DI, (size_t)NXP * DI, (size_t)M * NX);
        int n4 = 2 * M * NX / 4;
        xdbl_reduce_kernel<<<cdiv(n4, 256), 256>>>();
    }

    // 4) dt = softplus(x_dbl[:, :48] @ W_dt^T + b_dt)
    {
        dim3 grid(DI / 128, M / 128, 2);
        gemm_dt<128,128,16,8,8><<<grid, 256>>>(
            p_xdbl, NX, (size_t)M * NX,
            W_dt[0], W_dt[1],
            p_dt, DI, (size_t)M * DI,
            M, DI, DTR, b_dt[0], b_dt[1]);
    }

    // 5) selective scan + gating -> y (fp16)
    {
        dim3 grid(DI / 32, BB, 2);
        scan_kernel<<<grid, 256>>>(A_log[0], Dvec[0], A_log[1], Dvec[1]);
    }

    // 6) out = x + y0 @ W0^T + flip(y1) @ W1^T  (fp16 HMMA single-product)
    {
        dim3 grid(DIMM / 128, M / 64, 1);
        mma_gemm<1, 64><<<grid, 256, SMEM_G1>>>(
            p_yf, p_wout,
            out, x,
            DI, DIMM,
            (size_t)M * DI, (size_t)DIMM * DI, 0);
    }

    (void)in_sizes; (void)n_in; (void)out_size;
}

// round 15
// speedup vs baseline: 1.8159x; 1.0495x over previous
#include <cuda_runtime.h>
#include <cuda_fp16.h>
#include <math.h>
#include <stdint.h>

#define BB   2
#define LL   1024
#define DIMM 768
#define DI   1536
#define DS   16
#define DTR  48
#define KDT  64   // padded K for dt HMMA
#define NX   80   // DTR + 2*DS
#define NXP  128  // padded N for xdbl HMMA
#define TT   64   // scan time tile

typedef __half fp16;

// ---------------- device scratch ----------------
__device__ fp16  g_xz   [2 * BB * LL * 2 * DI];   // [dir][m][3072] fp16
__device__ float g_xdbl [2 * BB * LL * NX];       // fp32 (B/C for scan)
__device__ float g_xdblp[2 * 2 * BB * LL * NX];   // [ksplit][dir][m][nx]
__device__ fp16  g_xdt  [2 * BB * LL * KDT];      // dt_raw padded 48->64, fp16
__device__ fp16  g_dt   [2 * BB * LL * DI];       // softplus output, fp16

__device__ fp16 g_x_f  [BB * LL * DIMM];
__device__ fp16 g_win  [2 * 2 * DI * DIMM];
__device__ fp16 g_wout [2 * DIMM * DI];
__device__ fp16 g_wx   [2 * NXP * DI];            // zero-padded rows 80..127
__device__ fp16 g_wdt  [2 * DI * KDT];            // row-padded 48->64
__device__ fp16 g_xc_f [2 * BB * LL * DI];
__device__ fp16 g_y_f  [2 * BB * LL * DI];

__device__ __forceinline__ int fliprow(int m) {
    return (m & ~1023) + (1023 - (m & 1023));
}

__device__ __forceinline__ uint32_t smem_u32(const void* p) {
    uint32_t a;
    asm("{ .reg .u64 t; cvta.to.shared.u64 t, %1; cvt.u32.u64 %0, t; }" : "=r"(a) : "l"(p));
    return a;
}

__device__ __forceinline__ void ldmx4(uint32_t* r, uint32_t addr) {
    asm volatile("ldmatrix.sync.aligned.m8n8.x4.shared.b16 {%0,%1,%2,%3}, [%4];"
        : "=r"(r[0]), "=r"(r[1]), "=r"(r[2]), "=r"(r[3]) : "r"(addr));
}

__device__ __forceinline__ void mma16816(float* d, const uint32_t* a, const uint32_t* b) {
    asm volatile("mma.sync.aligned.m16n8k16.row.col.f32.f16.f16.f32 "
        "{%0,%1,%2,%3}, {%4,%5,%6,%7}, {%8,%9}, {%0,%1,%2,%3};"
        : "+f"(d[0]), "+f"(d[1]), "+f"(d[2]), "+f"(d[3])
        : "r"(a[0]), "r"(a[1]), "r"(a[2]), "r"(a[3]), "r"(b[0]), "r"(b[1]));
}

__device__ __forceinline__ void cp_async16(uint32_t dst, const void* src) {
    asm volatile("cp.async.cg.shared.global [%0], [%1], 16;" :: "r"(dst), "l"(src));
}
__device__ __forceinline__ void cp_commit() {
    asm volatile("cp.async.commit_group;" ::: "memory");
}
template<int N>
__device__ __forceinline__ void cp_wait() {
    asm volatile("cp.async.wait_group %0;" :: "n"(N) : "memory");
}

__device__ __forceinline__ float softplusf(float v) {
    return (v > 20.f) ? v : log1pf(expf(v));
}

// =======================================================================
// HMMA fp16 single-product GEMM, BK=64 chunks, 2-stage cp.async ring.
// MODE 0 (xz):   dir = blockIdx.z; A = x (flip if dir); C fp16 [dir]
// MODE 1 (wout): C fp32 = X + sum_dir A(y[dir], flip if dir) @ W[dir]^T
// MODE 2 (xdbl): dir=blockIdx.z; ksplit=blockIdx.x (n0=0); C fp32 partial
//                slab [ksplit*2+dir], store cols < NX only
// MODE 3 (dt):   dir = blockIdx.z; no flip; single K chunk;
//                C fp16 = softplus(v + bias[col]); bias = dir? X1 : X
// BN=128.
// =======================================================================
template<int MODE, int BM>
__global__ void __launch_bounds__(256)
mma_gemm(const fp16* __restrict__ A, const fp16* __restrict__ W,
         void* __restrict__ Cv, const float* __restrict__ X, const float* __restrict__ X1,
         int K, int ldc, size_t aDirStride, size_t wDirStride, size_t cDirStride)
{
    constexpr int NWM = BM / 32;
    constexpr int NWN = 8 / NWM;
    constexpr int WNW = 128 / NWN;
    constexpr int NAT = WNW / 8;
    constexpr int AV  = BM * 8 / 256;     // vec16 per thread for A tile (row=128B)
    constexpr int ARS = 144;              // smem row stride: 128 data + 16 pad
    constexpr int T_A = 0;
    constexpr int T_W = BM * ARS;
    constexpr int STAGE = (BM + 128) * ARS;

    extern __shared__ __align__(128) unsigned char smem[];
    const uint32_t smem_u = smem_u32(smem);

    const int tid  = threadIdx.x;
    const int wid  = tid >> 5;
    const int lane = tid & 31;
    const int warp_m = wid % NWM;
    const int warp_n = wid / NWM;
    const int m0 = blockIdx.y * BM;
    const int n0 = (MODE == 2) ? 0 : blockIdx.x * 128;

    const int quad = lane >> 3, liq = lane & 7;
    const int khB = (quad >> 1) * 16;
    uint32_t aOff[2], bOff[NAT / 2];
#pragma unroll
    for (int ma = 0; ma < 2; ma++) {
        int r = warp_m * 32 + ma * 16 + (quad & 1) * 8 + liq;
        aOff[ma] = r * ARS + khB;
    }
#pragma unroll
    for (int p = 0; p < NAT / 2; p++) {
        int r = warp_n * WNW + p * 16 + (quad & 1) * 8 + liq;
        bOff[p] = r * ARS + khB;
    }

    int a_row[AV], a_c16[AV];
#pragma unroll
    for (int i = 0; i < AV; i++) {
        int v = tid + i * 256;
        a_row[i] = v >> 3; a_c16[i] = v & 7;
    }
    int b_row[4], b_c16[4];
#pragma unroll
    for (int i = 0; i < 4; i++) {
        int v = tid + i * 256;
        b_row[i] = v >> 3; b_c16[i] = v & 7;
    }

    float acc[2][NAT][4];
#pragma unroll
    for (int ma = 0; ma < 2; ma++)
#pragma unroll
        for (int na = 0; na < NAT; na++)
#pragma unroll
            for (int j = 0; j < 4; j++) acc[ma][na][j] = 0.f;

    const int chunksPerK = (MODE == 2) ? (K / 128) : (K / 64);
    const int total = (MODE == 1) ? 2 * chunksPerK : chunksPerK;
    const int kbase = (MODE == 2) ? blockIdx.x * (K / 2) : 0;

    auto issue_stage = [&](int c, int s) {
        const int dir = (MODE == 1) ? (c / chunksPerK) : blockIdx.z;
        const int kc = kbase + (c % chunksPerK) * 64;
        const fp16* AP = A + (size_t)dir * aDirStride;
        const fp16* WP = W + (size_t)dir * wDirStride;
        const bool flip = (MODE == 0 || MODE == 1) && (dir == 1);
        const uint32_t base = smem_u + s * STAGE;
#pragma unroll
        for (int i = 0; i < AV; i++) {
            int m = m0 + a_row[i];
            int row = flip ? fliprow(m) : m;
            cp_async16(base + T_A + a_row[i] * ARS + a_c16[i] * 16,
                       AP + (size_t)row * K + kc + a_c16[i] * 8);
        }
#pragma unroll
        for (int i = 0; i < 4; i++) {
            cp_async16(base + T_W + b_row[i] * ARS + b_c16[i] * 16,
                       WP + (size_t)(n0 + b_row[i]) * K + kc + b_c16[i] * 8);
        }
        cp_commit();
    };

    issue_stage(0, 0);

    for (int c = 0; c < total; c++) {
        if (c + 1 < total) { issue_stage(c + 1, (c + 1) & 1); cp_wait<1>(); }
        else               { cp_wait<0>(); }
        __syncthreads();

        const uint32_t sbase = smem_u + (c & 1) * STAGE;
#pragma unroll
        for (int ks = 0; ks < 4; ks++) {
            const int ko = ks * 32;
            uint32_t a[2][4];
            ldmx4(a[0], sbase + T_A + aOff[0] + ko);
            ldmx4(a[1], sbase + T_A + aOff[1] + ko);
            uint32_t bw[NAT][2];
#pragma unroll
            for (int p = 0; p < NAT / 2; p++) {
                uint32_t r[4];
                ldmx4(r, sbase + T_W + bOff[p] + ko);
                bw[2*p][0] = r[0]; bw[2*p][1] = r[2];
                bw[2*p+1][0] = r[1]; bw[2*p+1][1] = r[3];
            }
#pragma unroll
            for (int ma = 0; ma < 2; ma++)
#pragma unroll
                for (int na = 0; na < NAT; na++)
                    mma16816(acc[ma][na], a[ma], bw[na]);
        }
        __syncthreads();
    }

    // epilogue
    const float* bias = (MODE == 3) ? (blockIdx.z ? X1 : X) : nullptr;
#pragma unroll
    for (int ma = 0; ma < 2; ma++) {
#pragma unroll
        for (int na = 0; na < NAT; na++) {
            int row = m0 + warp_m * 32 + ma * 16 + (lane >> 2);
            int col = n0 + warp_n * WNW + na * 8 + 2 * (lane & 3);
            if (MODE == 2 && col >= NX) continue;
            float v00 = acc[ma][na][0], v01 = acc[ma][na][1];
            float v10 = acc[ma][na][2], v11 = acc[ma][na][3];
            if (MODE == 0) {
                fp16* Cd = (fp16*)Cv + (size_t)blockIdx.z * cDirStride;
                *(__half2*)&Cd[(size_t)row * ldc + col] =
                    __halves2half2(__float2half_rn(v00), __float2half_rn(v01));
                *(__half2*)&Cd[(size_t)(row + 8) * ldc + col] =
                    __halves2half2(__float2half_rn(v10), __float2half_rn(v11));
            } else if (MODE == 3) {
                fp16* Cd = (fp16*)Cv + (size_t)blockIdx.z * cDirStride;
                float b0 = bias[col], b1 = bias[col + 1];
                *(__half2*)&Cd[(size_t)row * ldc + col] =
                    __halves2half2(__float2half_rn(softplusf(v00 + b0)),
                                   __float2half_rn(softplusf(v01 + b1)));
                *(__half2*)&Cd[(size_t)(row + 8) * ldc + col] =
                    __halves2half2(__float2half_rn(softplusf(v10 + b0)),
                                   __float2half_rn(softplusf(v11 + b1)));
            } else {
                float* Cd;
                if (MODE == 1) Cd = (float*)Cv;
                else           Cd = (float*)Cv + (size_t)(blockIdx.x * 2 + blockIdx.z) * cDirStride;
                if (MODE == 1) {
                    float2 x0 = *(const float2*)&X[(size_t)row * ldc + col];
                    float2 x1 = *(const float2*)&X[(size_t)(row + 8) * ldc + col];
                    v00 += x0.x; v01 += x0.y; v10 += x1.x; v11 += x1.y;
                }
                *(float2*)&Cd[(size_t)row * ldc + col] = make_float2(v00, v01);
                *(float2*)&Cd[(size_t)(row + 8) * ldc + col] = make_float2(v10, v11);
            }
        }
    }
}

// ==================== xdbl partial reduce (fp32 out + fp16 padded dt copy) ====================
__global__ void xdbl_reduce_kernel()
{
    const int N4 = 2 * BB * LL * NX / 4;   // float4 count of one k-half
    int i = blockIdx.x * blockDim.x + threadIdx.x;
    if (i >= N4) return;
    const float4* P = (const float4*)g_xdblp;
    float4 a = P[i];
    float4 b = P[i + N4];
    a.x += b.x; a.y += b.y; a.z += b.z; a.w += b.w;
    ((float4*)g_xdbl)[i] = a;

    // fp16 dt copy, padded: row-local cols [0,48) data, [48,64) zeros
    const int GPR = NX / 4;              // 20 float4 groups per row
    int row = i / GPR, colG = i % GPR;
    if (colG < KDT / 4) {
        __half2 h0, h1;
        if (colG < DTR / 4) {
            h0 = __halves2half2(__float2half_rn(a.x), __float2half_rn(a.y));
            h1 = __halves2half2(__float2half_rn(a.z), __float2half_rn(a.w));
        } else {
            h0 = __halves2half2(__float2half_rn(0.f), __float2half_rn(0.f));
            h1 = h0;
        }
        __half2* d = (__half2*)&g_xdt[(size_t)row * KDT + colG * 4];
        d[0] = h0; d[1] = h1;
    }
}

// ==================== fused fp16 convert prep (9 regions, row padding) ====================
struct SplitArgs {
    const float* src[9];
    fp16* dst[9];
    int nG[9];        // total dst groups (4 elems each)
    int rowSrcG[9];   // src groups per row
    int rowDstG[9];   // dst groups per row
};

__global__ void split_all_kernel(SplitArgs a)
{
    const int r = blockIdx.y;
    int i = blockIdx.x * blockDim.x + threadIdx.x;
    if (i >= a.nG[r]) return;
    int row = i / a.rowDstG[r];
    int colG = i - row * a.rowDstG[r];
    float4 v = (colG < a.rowSrcG[r])
             ? ((const float4*)a.src[r])[(size_t)row * a.rowSrcG[r] + colG]
             : make_float4(0.f, 0.f, 0.f, 0.f);
    ((__half2*)a.dst[r])[2*i]   = __halves2half2(__float2half_rn(v.x), __float2half_rn(v.y));
    ((__half2*)a.dst[r])[2*i+1] = __halves2half2(__float2half_rn(v.z), __float2half_rn(v.w));
}

// ==================== conv + silu (fp16 in, fp16 out) ====================
__global__ void conv_silu_kernel(const float* __restrict__ cw_f, const float* __restrict__ cb_f,
                                 const float* __restrict__ cw_b, const float* __restrict__ cb_b)
{
    const int TOT4 = 2 * BB * LL * DI / 4;
    int idx = blockIdx.x * blockDim.x + threadIdx.x;
    if (idx >= TOT4) return;
    const int DQ = DI / 4;
    int dq = idx % DQ;
    int r = idx / DQ;
    int t = r % LL; r /= LL;
    int b = r % BB;
    int dir = r / BB;
    int d4 = dq * 4;
    const float* w  = dir ? cw_b : cw_f;
    const float* cb = dir ? cb_b : cb_f;
    const fp16* xp = g_xz + ((size_t)(dir * BB + b)) * LL * 2 * DI;

    float4 wr0 = *(const float4*)&w[(d4+0)*4];
    float4 wr1 = *(const float4*)&w[(d4+1)*4];
    float4 wr2 = *(const float4*)&w[(d4+2)*4];
    float4 wr3 = *(const float4*)&w[(d4+3)*4];
    float4 s = *(const float4*)&cb[d4];
#pragma unroll
    for (int k = 0; k < 4; k++) {
        int tt = t + k - 3;
        if (tt >= 0) {
            const __half2* xv = (const __half2*)&xp[(size_t)tt * 2 * DI + d4];
            float2 x0 = __half22float2(xv[0]);
            float2 x1 = __half22float2(xv[1]);
            s.x += ((const float*)&wr0)[k] * x0.x;
            s.y += ((const float*)&wr1)[k] * x0.y;
            s.z += ((const float*)&wr2)[k] * x1.x;
            s.w += ((const float*)&wr3)[k] * x1.y;
        }
    }
    s.x = s.x / (1.f + __expf(-s.x));
    s.y = s.y / (1.f + __expf(-s.y));
    s.z = s.z / (1.f + __expf(-s.z));
    s.w = s.w / (1.f + __expf(-s.w));

    ((__half2*)g_xc_f)[2*idx]   = __halves2half2(__float2half_rn(s.x), __float2half_rn(s.y));
    ((__half2*)g_xc_f)[2*idx+1] = __halves2half2(__float2half_rn(s.z), __float2half_rn(s.w));
}

// ==================== selective scan (smem time-tiled, fp16 streams) ====================
__global__ void __launch_bounds__(256)
scan_kernel(const float* __restrict__ Alog_f, const float* __restrict__ D_f,
            const float* __restrict__ Alog_b, const float* __restrict__ D_b)
{
    __shared__ float s_dt[TT][32], s_xc[TT][32], s_z[TT][32], s_bc[TT][32];
    __shared__ fp16  s_y[TT][32];

    const int tid = threadIdx.x;
    const int s4 = tid & 7;
    const int dl = tid >> 3;
    const int d0  = blockIdx.x * 32;
    const int b   = blockIdx.y;
    const int dir = blockIdx.z;

    const float* Alog = dir ? Alog_b : Alog_f;
    const float* Dp   = dir ? D_b   : D_f;

    const size_t base_di = ((size_t)(dir * BB + b)) * LL * DI;
    const size_t base_x  = ((size_t)(dir * BB + b)) * LL * NX;
    const size_t base_z  = ((size_t)(dir * BB + b)) * LL * 2 * DI + DI;

    float2 Av = *(const float2*)&Alog[(d0 + dl) * DS + 2*s4];
    const float A0 = -__expf(Av.x);
    const float A1 = -__expf(Av.y);
    const float Dv = Dp[d0 + dl];

    float h0 = 0.f, h1 = 0.f;

    for (int t0 = 0; t0 < LL; t0 += TT) {
#pragma unroll
        for (int i = tid; i < TT * 32; i += 256) {
            int t = i >> 5, d = i & 31;
            size_t r = base_di + (size_t)(t0 + t) * DI + d0 + d;
            s_dt[t][d] = __half2float(g_dt[r]);
            s_xc[t][d] = __half2float(g_xc_f[r]);
            s_z [t][d] = __half2float(g_xz[base_z + (size_t)(t0 + t) * 2 * DI + d0 + d]);
            s_bc[t][d] = g_xdbl[base_x + (size_t)(t0 + t) * NX + DTR + d];
        }
        __syncthreads();

#pragma unroll 8
        for (int t = 0; t < TT; t++) {
            float dtv = s_dt[t][dl];
            float xcv = s_xc[t][dl];
            float B0 = s_bc[t][2*s4],      B1 = s_bc[t][2*s4 + 1];
            float C0 = s_bc[t][16 + 2*s4], C1 = s_bc[t][17 + 2*s4];
            float dx  = dtv * xcv;
            h0 = __expf(dtv * A0) * h0 + dx * B0;
            h1 = __expf(dtv * A1) * h1 + dx * B1;
            float p = h0 * C0 + h1 * C1;
            p += __shfl_xor_sync(0xffffffffu, p, 4);
            p += __shfl_xor_sync(0xffffffffu, p, 2);
            p += __shfl_xor_sync(0xffffffffu, p, 1);
            if (s4 == 0) {
                float zv = s_z[t][dl];
                float y = p + xcv * Dv;
                float sig = 1.f / (1.f + __expf(-zv));
                y = y * (zv * sig);
                s_y[t][dl] = __float2half_rn(y);
            }
        }
        __syncthreads();

#pragma unroll
        for (int i = tid; i < TT * 32; i += 256) {
            int t = i >> 5, d = i & 31;
            g_y_f[base_di + (size_t)(t0 + t) * DI + d0 + d] = s_y[t][d];
        }
        __syncthreads();
    }
}

static inline int cdiv(int a, int b) { return (a + b - 1) / b; }

extern "C" void kernel_launch(void* const* d_in, const int* in_sizes, int n_in,
                              void* d_out, int out_size)
{
    const float* x = (const float*)d_in[0];
    const float* W_in[2]   = { (const float*)d_in[1],  (const float*)d_in[10] };
    const float* conv_w[2] = { (const float*)d_in[2],  (const float*)d_in[11] };
    const float* conv_b[2] = { (const float*)d_in[3],  (const float*)d_in[12] };
    const float* W_x[2]    = { (const float*)d_in[4],  (const float*)d_in[13] };
    const float* W_dt[2]   = { (const float*)d_in[5],  (const float*)d_in[14] };
    const float* b_dt[2]   = { (const float*)d_in[6],  (const float*)d_in[15] };
    const float* A_log[2]  = { (const float*)d_in[7],  (const float*)d_in[16] };
    const float* Dvec[2]   = { (const float*)d_in[8],  (const float*)d_in[17] };
    const float* W_out[2]  = { (const float*)d_in[9],  (const float*)d_in[18] };
    float* out = (float*)d_out;

    float *p_xdblp;
    cudaGetSymbolAddress((void**)&p_xdblp, g_xdblp);
    fp16 *p_xz, *p_xdt, *p_dt;
    cudaGetSymbolAddress((void**)&p_xz,  g_xz);
    cudaGetSymbolAddress((void**)&p_xdt, g_xdt);
    cudaGetSymbolAddress((void**)&p_dt,  g_dt);
    fp16 *p_xf, *p_win, *p_wout, *p_wx, *p_wdt, *p_xcf, *p_yf;
    cudaGetSymbolAddress((void**)&p_xf,   g_x_f);
    cudaGetSymbolAddress((void**)&p_win,  g_win);
    cudaGetSymbolAddress((void**)&p_wout, g_wout);
    cudaGetSymbolAddress((void**)&p_wx,   g_wx);
    cudaGetSymbolAddress((void**)&p_wdt,  g_wdt);
    cudaGetSymbolAddress((void**)&p_xcf,  g_xc_f);
    cudaGetSymbolAddress((void**)&p_yf,   g_y_f);

    const int M = BB * LL;  // 2048

    const int SMEM_G0 = 2 * (128 + 128) * 144;   // 73728
    const int SMEM_G1 = 2 * (64 + 128) * 144;    // 55296
    cudaFuncSetAttribute(mma_gemm<0,128>, cudaFuncAttributeMaxDynamicSharedMemorySize, SMEM_G0);
    cudaFuncSetAttribute(mma_gemm<1,64>,  cudaFuncAttributeMaxDynamicSharedMemorySize, SMEM_G1);
    cudaFuncSetAttribute(mma_gemm<2,64>,  cudaFuncAttributeMaxDynamicSharedMemorySize, SMEM_G1);
    cudaFuncSetAttribute(mma_gemm<3,64>,  cudaFuncAttributeMaxDynamicSharedMemorySize, SMEM_G1);

    // 0) fp16 converts (one launch, 9 regions; wx tail-padded, wdt row-padded)
    {
        SplitArgs a;
        auto lin = [&](int r, const float* s, fp16* d, int n4) {
            a.src[r] = s; a.dst[r] = d; a.nG[r] = n4; a.rowSrcG[r] = 1; a.rowDstG[r] = 1;
        };
        lin(0, x,        p_xf,   M * DIMM / 4);
        lin(1, W_in[0],  p_win,  2 * DI * DIMM / 4);
        lin(2, W_in[1],  p_win + (size_t)2*DI*DIMM, 2 * DI * DIMM / 4);
        lin(3, W_out[0], p_wout, DIMM * DI / 4);
        lin(4, W_out[1], p_wout + (size_t)DIMM*DI, DIMM * DI / 4);
        // W_x: tail pad rows 80..127 (one giant "row")
        a.src[5] = W_x[0]; a.dst[5] = p_wx;
        a.nG[5] = NXP * DI / 4; a.rowSrcG[5] = NX * DI / 4; a.rowDstG[5] = NXP * DI / 4;
        a.src[6] = W_x[1]; a.dst[6] = p_wx + (size_t)NXP*DI;
        a.nG[6] = NXP * DI / 4; a.rowSrcG[6] = NX * DI / 4; a.rowDstG[6] = NXP * DI / 4;
        // W_dt: per-row pad 48 -> 64
        a.src[7] = W_dt[0]; a.dst[7] = p_wdt;
        a.nG[7] = DI * KDT / 4; a.rowSrcG[7] = DTR / 4; a.rowDstG[7] = KDT / 4;
        a.src[8] = W_dt[1]; a.dst[8] = p_wdt + (size_t)DI*KDT;
        a.nG[8] = DI * KDT / 4; a.rowSrcG[8] = DTR / 4; a.rowDstG[8] = KDT / 4;

        int maxn4 = 2 * DI * DIMM / 4;
        dim3 grid(cdiv(maxn4, 256), 9);
        split_all_kernel<<<grid, 256>>>(a);
    }

    // 1) xz = x(+flip) @ W_in^T  -> fp16
    {
        dim3 grid(2 * DI / 128, M / 128, 2);
        mma_gemm<0, 128><<<grid, 256, SMEM_G0>>>(
            p_xf, p_win,
            p_xz, nullptr, nullptr,
            DIMM, 2 * DI,
            0, (size_t)2*DI*DIMM, (size_t)M * 2 * DI);
    }

    // 2) conv + silu -> g_xc_f (fp16)
    {
        int n4 = 2 * BB * LL * DI / 4;
        conv_silu_kernel<<<cdiv(n4, 256), 256>>>(conv_w[0], conv_b[0], conv_w[1], conv_b[1]);
    }

    // 3) x_dbl = xc @ W_x^T  (MODE 2, split-K2, partials + reduce -> fp32 + fp16 dt copy)
    {
        dim3 grid(2, M / 64, 2);
        mma_gemm<2, 64><<<grid, 256, SMEM_G1>>>(
            p_xcf, p_wx,
            p_xdblp, nullptr, nullptr,
            DI, NX,
            (size_t)M * DI, (size_t)NXP * DI, (size_t)M * NX);
        int n4 = 2 * M * NX / 4;
        xdbl_reduce_kernel<<<cdiv(n4, 256), 256>>>();
    }

    // 4) dt = softplus(xdt @ W_dt^T + b_dt)  (MODE 3, K=64 single chunk)
    {
        dim3 grid(DI / 128, M / 64, 2);
        mma_gemm<3, 64><<<grid, 256, SMEM_G1>>>(
            p_xdt, p_wdt,
            p_dt, b_dt[0], b_dt[1],
            KDT, DI,
            (size_t)M * KDT, (size_t)DI * KDT, (size_t)M * DI);
    }

    // 5) selective scan + gating -> y (fp16)
    {
        dim3 grid(DI / 32, BB, 2);
        scan_kernel<<<grid, 256>>>(A_log[0], Dvec[0], A_log[1], Dvec[1]);
    }

    // 6) out = x + y0 @ W0^T + flip(y1) @ W1^T  (MODE 1, fp32 + residual)
    {
        dim3 grid(DIMM / 128, M / 64, 1);
        mma_gemm<1, 64><<<grid, 256, SMEM_G1>>>(
            p_yf, p_wout,
            out, x, nullptr,
            DI, DIMM,
            (size_t)M * DI, (size_t)DIMM * DI, 0);
    }

    (void)in_sizes; (void)n_in; (void)out_size;
}

// round 16
// speedup vs baseline: 1.8211x; 1.0028x over previous
#include <cuda_runtime.h>
#include <cuda_fp16.h>
#include <math.h>
#include <stdint.h>

#define BB   2
#define LL   1024
#define DIMM 768
#define DI   1536
#define DS   16
#define DTR  48
#define KDT  64   // padded K for dt HMMA
#define NX   80   // DTR + 2*DS
#define NXP  128  // padded N for xdbl HMMA
#define TT   64   // scan time tile

typedef __half fp16;

// ---------------- device scratch ----------------
__device__ fp16  g_xz   [2 * BB * LL * 2 * DI];   // [dir][m][3072] fp16
__device__ float g_xdbl [2 * BB * LL * NX];       // fp32 (B/C for scan)
__device__ float g_xdblp[2 * 2 * BB * LL * NX];   // [ksplit][dir][m][nx]
__device__ fp16  g_xdt  [2 * BB * LL * KDT];      // dt_raw padded 48->64, fp16
__device__ fp16  g_dt   [2 * BB * LL * DI];       // softplus output, fp16

__device__ fp16 g_x_f  [BB * LL * DIMM];
__device__ fp16 g_win  [2 * 2 * DI * DIMM];
__device__ fp16 g_wout [2 * DIMM * DI];
__device__ fp16 g_wx   [2 * NXP * DI];            // zero-padded rows 80..127
__device__ fp16 g_wdt  [2 * DI * KDT];            // row-padded 48->64
__device__ fp16 g_xc_f [2 * BB * LL * DI];
__device__ fp16 g_y_f  [2 * BB * LL * DI];

__device__ __forceinline__ int fliprow(int m) {
    return (m & ~1023) + (1023 - (m & 1023));
}

__device__ __forceinline__ uint32_t smem_u32(const void* p) {
    uint32_t a;
    asm("{ .reg .u64 t; cvta.to.shared.u64 t, %1; cvt.u32.u64 %0, t; }" : "=r"(a) : "l"(p));
    return a;
}

__device__ __forceinline__ void ldmx4(uint32_t* r, uint32_t addr) {
    asm volatile("ldmatrix.sync.aligned.m8n8.x4.shared.b16 {%0,%1,%2,%3}, [%4];"
        : "=r"(r[0]), "=r"(r[1]), "=r"(r[2]), "=r"(r[3]) : "r"(addr));
}

__device__ __forceinline__ void mma16816(float* d, const uint32_t* a, const uint32_t* b) {
    asm volatile("mma.sync.aligned.m16n8k16.row.col.f32.f16.f16.f32 "
        "{%0,%1,%2,%3}, {%4,%5,%6,%7}, {%8,%9}, {%0,%1,%2,%3};"
        : "+f"(d[0]), "+f"(d[1]), "+f"(d[2]), "+f"(d[3])
        : "r"(a[0]), "r"(a[1]), "r"(a[2]), "r"(a[3]), "r"(b[0]), "r"(b[1]));
}

__device__ __forceinline__ void cp_async16(uint32_t dst, const void* src) {
    asm volatile("cp.async.cg.shared.global [%0], [%1], 16;" :: "r"(dst), "l"(src));
}
__device__ __forceinline__ void cp_commit() {
    asm volatile("cp.async.commit_group;" ::: "memory");
}
template<int N>
__device__ __forceinline__ void cp_wait() {
    asm volatile("cp.async.wait_group %0;" :: "n"(N) : "memory");
}

__device__ __forceinline__ float softplusf(float v) {
    return (v > 20.f) ? v : log1pf(expf(v));
}

// =======================================================================
// HMMA fp16 single-product GEMM, BK=64 chunks, 2-stage ring,
// ONE __syncthreads per chunk (wait -> sync -> issue-next -> compute).
// NT = threads per CTA (256 or 512).
// MODE 0 (xz):   dir = blockIdx.z; A = x (flip if dir); C fp16 [dir]
// MODE 1 (wout): C fp32 = X + sum_dir A(y[dir], flip if dir) @ W[dir]^T
// MODE 2 (xdbl): dir=blockIdx.z; ksplit=blockIdx.x (n0=0); C fp32 partial
//                slab [ksplit*2+dir], store cols < NX only
// MODE 3 (dt):   dir = blockIdx.z; no flip; single K chunk;
//                C fp16 = softplus(v + bias[col]); bias = dir? X1 : X
// BN=128.
// =======================================================================
template<int MODE, int BM, int NT>
__global__ void __launch_bounds__(NT, 2)
mma_gemm(const fp16* __restrict__ A, const fp16* __restrict__ W,
         void* __restrict__ Cv, const float* __restrict__ X, const float* __restrict__ X1,
         int K, int ldc, size_t aDirStride, size_t wDirStride, size_t cDirStride)
{
    constexpr int NWARPS = NT / 32;
    constexpr int NWM = BM / 32;
    constexpr int NWN = NWARPS / NWM;
    constexpr int WNW = 128 / NWN;
    constexpr int NAT = WNW / 8;
    constexpr int AV  = BM * 8 / NT;      // vec16 per thread for A tile (row=128B)
    constexpr int BV  = 128 * 8 / NT;
    constexpr int ARS = 144;              // smem row stride: 128 data + 16 pad
    constexpr int T_A = 0;
    constexpr int T_W = BM * ARS;
    constexpr int STAGE = (BM + 128) * ARS;

    extern __shared__ __align__(128) unsigned char smem[];
    const uint32_t smem_u = smem_u32(smem);

    const int tid  = threadIdx.x;
    const int wid  = tid >> 5;
    const int lane = tid & 31;
    const int warp_m = wid % NWM;
    const int warp_n = wid / NWM;
    const int m0 = blockIdx.y * BM;
    const int n0 = (MODE == 2) ? 0 : blockIdx.x * 128;

    const int quad = lane >> 3, liq = lane & 7;
    const int khB = (quad >> 1) * 16;
    uint32_t aOff[2], bOff[NAT / 2];
#pragma unroll
    for (int ma = 0; ma < 2; ma++) {
        int r = warp_m * 32 + ma * 16 + (quad & 1) * 8 + liq;
        aOff[ma] = r * ARS + khB;
    }
#pragma unroll
    for (int p = 0; p < NAT / 2; p++) {
        int r = warp_n * WNW + p * 16 + (quad & 1) * 8 + liq;
        bOff[p] = r * ARS + khB;
    }

    int a_row[AV], a_c16[AV];
#pragma unroll
    for (int i = 0; i < AV; i++) {
        int v = tid + i * NT;
        a_row[i] = v >> 3; a_c16[i] = v & 7;
    }
    int b_row[BV], b_c16[BV];
#pragma unroll
    for (int i = 0; i < BV; i++) {
        int v = tid + i * NT;
        b_row[i] = v >> 3; b_c16[i] = v & 7;
    }

    float acc[2][NAT][4];
#pragma unroll
    for (int ma = 0; ma < 2; ma++)
#pragma unroll
        for (int na = 0; na < NAT; na++)
#pragma unroll
            for (int j = 0; j < 4; j++) acc[ma][na][j] = 0.f;

    const int chunksPerK = (MODE == 2) ? (K / 128) : (K / 64);
    const int total = (MODE == 1) ? 2 * chunksPerK : chunksPerK;
    const int kbase = (MODE == 2) ? blockIdx.x * (K / 2) : 0;

    auto issue_stage = [&](int c, int s) {
        const int dir = (MODE == 1) ? (c / chunksPerK) : blockIdx.z;
        const int kc = kbase + (c % chunksPerK) * 64;
        const fp16* AP = A + (size_t)dir * aDirStride;
        const fp16* WP = W + (size_t)dir * wDirStride;
        const bool flip = (MODE == 0 || MODE == 1) && (dir == 1);
        const uint32_t base = smem_u + s * STAGE;
#pragma unroll
        for (int i = 0; i < AV; i++) {
            int m = m0 + a_row[i];
            int row = flip ? fliprow(m) : m;
            cp_async16(base + T_A + a_row[i] * ARS + a_c16[i] * 16,
                       AP + (size_t)row * K + kc + a_c16[i] * 8);
        }
#pragma unroll
        for (int i = 0; i < BV; i++) {
            cp_async16(base + T_W + b_row[i] * ARS + b_c16[i] * 16,
                       WP + (size_t)(n0 + b_row[i]) * K + kc + b_c16[i] * 8);
        }
        cp_commit();
    };

    issue_stage(0, 0);

    for (int c = 0; c < total; c++) {
        cp_wait<0>();
        __syncthreads();                 // stage c ready AND compute(c-1) retired
        if (c + 1 < total) issue_stage(c + 1, (c + 1) & 1);

        const uint32_t sbase = smem_u + (c & 1) * STAGE;
#pragma unroll
        for (int ks = 0; ks < 4; ks++) {
            const int ko = ks * 32;
            uint32_t a[2][4];
            ldmx4(a[0], sbase + T_A + aOff[0] + ko);
            ldmx4(a[1], sbase + T_A + aOff[1] + ko);
            uint32_t bw[NAT][2];
#pragma unroll
            for (int p = 0; p < NAT / 2; p++) {
                uint32_t r[4];
                ldmx4(r, sbase + T_W + bOff[p] + ko);
                bw[2*p][0] = r[0]; bw[2*p][1] = r[2];
                bw[2*p+1][0] = r[1]; bw[2*p+1][1] = r[3];
            }
#pragma unroll
            for (int ma = 0; ma < 2; ma++)
#pragma unroll
                for (int na = 0; na < NAT; na++)
                    mma16816(acc[ma][na], a[ma], bw[na]);
        }
    }

    // epilogue
    const float* bias = (MODE == 3) ? (blockIdx.z ? X1 : X) : nullptr;
#pragma unroll
    for (int ma = 0; ma < 2; ma++) {
#pragma unroll
        for (int na = 0; na < NAT; na++) {
            int row = m0 + warp_m * 32 + ma * 16 + (lane >> 2);
            int col = n0 + warp_n * WNW + na * 8 + 2 * (lane & 3);
            if (MODE == 2 && col >= NX) continue;
            float v00 = acc[ma][na][0], v01 = acc[ma][na][1];
            float v10 = acc[ma][na][2], v11 = acc[ma][na][3];
            if (MODE == 0) {
                fp16* Cd = (fp16*)Cv + (size_t)blockIdx.z * cDirStride;
                *(__half2*)&Cd[(size_t)row * ldc + col] =
                    __halves2half2(__float2half_rn(v00), __float2half_rn(v01));
                *(__half2*)&Cd[(size_t)(row + 8) * ldc + col] =
                    __halves2half2(__float2half_rn(v10), __float2half_rn(v11));
            } else if (MODE == 3) {
                fp16* Cd = (fp16*)Cv + (size_t)blockIdx.z * cDirStride;
                float b0 = bias[col], b1 = bias[col + 1];
                *(__half2*)&Cd[(size_t)row * ldc + col] =
                    __halves2half2(__float2half_rn(softplusf(v00 + b0)),
                                   __float2half_rn(softplusf(v01 + b1)));
                *(__half2*)&Cd[(size_t)(row + 8) * ldc + col] =
                    __halves2half2(__float2half_rn(softplusf(v10 + b0)),
                                   __float2half_rn(softplusf(v11 + b1)));
            } else {
                float* Cd;
                if (MODE == 1) Cd = (float*)Cv;
                else           Cd = (float*)Cv + (size_t)(blockIdx.x * 2 + blockIdx.z) * cDirStride;
                if (MODE == 1) {
                    float2 x0 = *(const float2*)&X[(size_t)row * ldc + col];
                    float2 x1 = *(const float2*)&X[(size_t)(row + 8) * ldc + col];
                    v00 += x0.x; v01 += x0.y; v10 += x1.x; v11 += x1.y;
                }
                *(float2*)&Cd[(size_t)row * ldc + col] = make_float2(v00, v01);
                *(float2*)&Cd[(size_t)(row + 8) * ldc + col] = make_float2(v10, v11);
            }
        }
    }
}

// ==================== xdbl partial reduce (fp32 out + fp16 padded dt copy) ====================
__global__ void xdbl_reduce_kernel()
{
    const int N4 = 2 * BB * LL * NX / 4;   // float4 count of one k-half
    int i = blockIdx.x * blockDim.x + threadIdx.x;
    if (i >= N4) return;
    const float4* P = (const float4*)g_xdblp;
    float4 a = P[i];
    float4 b = P[i + N4];
    a.x += b.x; a.y += b.y; a.z += b.z; a.w += b.w;
    ((float4*)g_xdbl)[i] = a;

    // fp16 dt copy, padded: row-local cols [0,48) data, [48,64) zeros
    const int GPR = NX / 4;              // 20 float4 groups per row
    int row = i / GPR, colG = i % GPR;
    if (colG < KDT / 4) {
        __half2 h0, h1;
        if (colG < DTR / 4) {
            h0 = __halves2half2(__float2half_rn(a.x), __float2half_rn(a.y));
            h1 = __halves2half2(__float2half_rn(a.z), __float2half_rn(a.w));
        } else {
            h0 = __halves2half2(__float2half_rn(0.f), __float2half_rn(0.f));
            h1 = h0;
        }
        __half2* d = (__half2*)&g_xdt[(size_t)row * KDT + colG * 4];
        d[0] = h0; d[1] = h1;
    }
}

// ==================== fused fp16 convert prep (9 regions, row padding) ====================
struct SplitArgs {
    const float* src[9];
    fp16* dst[9];
    int nG[9];
    int rowSrcG[9];
    int rowDstG[9];
};

__global__ void split_all_kernel(SplitArgs a)
{
    const int r = blockIdx.y;
    int i = blockIdx.x * blockDim.x + threadIdx.x;
    if (i >= a.nG[r]) return;
    int row = i / a.rowDstG[r];
    int colG = i - row * a.rowDstG[r];
    float4 v = (colG < a.rowSrcG[r])
             ? ((const float4*)a.src[r])[(size_t)row * a.rowSrcG[r] + colG]
             : make_float4(0.f, 0.f, 0.f, 0.f);
    ((__half2*)a.dst[r])[2*i]   = __halves2half2(__float2half_rn(v.x), __float2half_rn(v.y));
    ((__half2*)a.dst[r])[2*i+1] = __halves2half2(__float2half_rn(v.z), __float2half_rn(v.w));
}

// ==================== conv + silu (fp16 in, fp16 out) ====================
__global__ void conv_silu_kernel(const float* __restrict__ cw_f, const float* __restrict__ cb_f,
                                 const float* __restrict__ cw_b, const float* __restrict__ cb_b)
{
    const int TOT4 = 2 * BB * LL * DI / 4;
    int idx = blockIdx.x * blockDim.x + threadIdx.x;
    if (idx >= TOT4) return;
    const int DQ = DI / 4;
    int dq = idx % DQ;
    int r = idx / DQ;
    int t = r % LL; r /= LL;
    int b = r % BB;
    int dir = r / BB;
    int d4 = dq * 4;
    const float* w  = dir ? cw_b : cw_f;
    const float* cb = dir ? cb_b : cb_f;
    const fp16* xp = g_xz + ((size_t)(dir * BB + b)) * LL * 2 * DI;

    float4 wr0 = *(const float4*)&w[(d4+0)*4];
    float4 wr1 = *(const float4*)&w[(d4+1)*4];
    float4 wr2 = *(const float4*)&w[(d4+2)*4];
    float4 wr3 = *(const float4*)&w[(d4+3)*4];
    float4 s = *(const float4*)&cb[d4];
#pragma unroll
    for (int k = 0; k < 4; k++) {
        int tt = t + k - 3;
        if (tt >= 0) {
            const __half2* xv = (const __half2*)&xp[(size_t)tt * 2 * DI + d4];
            float2 x0 = __half22float2(xv[0]);
            float2 x1 = __half22float2(xv[1]);
            s.x += ((const float*)&wr0)[k] * x0.x;
            s.y += ((const float*)&wr1)[k] * x0.y;
            s.z += ((const float*)&wr2)[k] * x1.x;
            s.w += ((const float*)&wr3)[k] * x1.y;
        }
    }
    s.x = s.x / (1.f + __expf(-s.x));
    s.y = s.y / (1.f + __expf(-s.y));
    s.z = s.z / (1.f + __expf(-s.z));
    s.w = s.w / (1.f + __expf(-s.w));

    ((__half2*)g_xc_f)[2*idx]   = __halves2half2(__float2half_rn(s.x), __float2half_rn(s.y));
    ((__half2*)g_xc_f)[2*idx+1] = __halves2half2(__float2half_rn(s.z), __float2half_rn(s.w));
}

// ==================== selective scan (smem time-tiled, fp16 streams) ====================
__global__ void __launch_bounds__(256)
scan_kernel(const float* __restrict__ Alog_f, const float* __restrict__ D_f,
            const float* __restrict__ Alog_b, const float* __restrict__ D_b)
{
    __shared__ float s_dt[TT][32], s_xc[TT][32], s_z[TT][32], s_bc[TT][32];
    __shared__ fp16  s_y[TT][32];

    const int tid = threadIdx.x;
    const int s4 = tid & 7;
    const int dl = tid >> 3;
    const int d0  = blockIdx.x * 32;
    const int b   = blockIdx.y;
    const int dir = blockIdx.z;

    const float* Alog = dir ? Alog_b : Alog_f;
    const float* Dp   = dir ? D_b   : D_f;

    const size_t base_di = ((size_t)(dir * BB + b)) * LL * DI;
    const size_t base_x  = ((size_t)(dir * BB + b)) * LL * NX;
    const size_t base_z  = ((size_t)(dir * BB + b)) * LL * 2 * DI + DI;

    float2 Av = *(const float2*)&Alog[(d0 + dl) * DS + 2*s4];
    const float A0 = -__expf(Av.x);
    const float A1 = -__expf(Av.y);
    const float Dv = Dp[d0 + dl];

    float h0 = 0.f, h1 = 0.f;

    for (int t0 = 0; t0 < LL; t0 += TT) {
#pragma unroll
        for (int i = tid; i < TT * 32; i += 256) {
            int t = i >> 5, d = i & 31;
            size_t r = base_di + (size_t)(t0 + t) * DI + d0 + d;
            s_dt[t][d] = __half2float(g_dt[r]);
            s_xc[t][d] = __half2float(g_xc_f[r]);
            s_z [t][d] = __half2float(g_xz[base_z + (size_t)(t0 + t) * 2 * DI + d0 + d]);
            s_bc[t][d] = g_xdbl[base_x + (size_t)(t0 + t) * NX + DTR + d];
        }
        __syncthreads();

#pragma unroll 8
        for (int t = 0; t < TT; t++) {
            float dtv = s_dt[t][dl];
            float xcv = s_xc[t][dl];
            float B0 = s_bc[t][2*s4],      B1 = s_bc[t][2*s4 + 1];
            float C0 = s_bc[t][16 + 2*s4], C1 = s_bc[t][17 + 2*s4];
            float dx  = dtv * xcv;
            h0 = __expf(dtv * A0) * h0 + dx * B0;
            h1 = __expf(dtv * A1) * h1 + dx * B1;
            float p = h0 * C0 + h1 * C1;
            p += __shfl_xor_sync(0xffffffffu, p, 4);
            p += __shfl_xor_sync(0xffffffffu, p, 2);
            p += __shfl_xor_sync(0xffffffffu, p, 1);
            if (s4 == 0) {
                float zv = s_z[t][dl];
                float y = p + xcv * Dv;
                float sig = 1.f / (1.f + __expf(-zv));
                y = y * (zv * sig);
                s_y[t][dl] = __float2half_rn(y);
            }
        }
        __syncthreads();

#pragma unroll
        for (int i = tid; i < TT * 32; i += 256) {
            int t = i >> 5, d = i & 31;
            g_y_f[base_di + (size_t)(t0 + t) * DI + d0 + d] = s_y[t][d];
        }
        __syncthreads();
    }
}

static inline int cdiv(int a, int b) { return (a + b - 1) / b; }

extern "C" void kernel_launch(void* const* d_in, const int* in_sizes, int n_in,
                              void* d_out, int out_size)
{
    const float* x = (const float*)d_in[0];
    const float* W_in[2]   = { (const float*)d_in[1],  (const float*)d_in[10] };
    const float* conv_w[2] = { (const float*)d_in[2],  (const float*)d_in[11] };
    const float* conv_b[2] = { (const float*)d_in[3],  (const float*)d_in[12] };
    const float* W_x[2]    = { (const float*)d_in[4],  (const float*)d_in[13] };
    const float* W_dt[2]   = { (const float*)d_in[5],  (const float*)d_in[14] };
    const float* b_dt[2]   = { (const float*)d_in[6],  (const float*)d_in[15] };
    const float* A_log[2]  = { (const float*)d_in[7],  (const float*)d_in[16] };
    const float* Dvec[2]   = { (const float*)d_in[8],  (const float*)d_in[17] };
    const float* W_out[2]  = { (const float*)d_in[9],  (const float*)d_in[18] };
    float* out = (float*)d_out;

    float *p_xdblp;
    cudaGetSymbolAddress((void**)&p_xdblp, g_xdblp);
    fp16 *p_xz, *p_xdt, *p_dt;
    cudaGetSymbolAddress((void**)&p_xz,  g_xz);
    cudaGetSymbolAddress((void**)&p_xdt, g_xdt);
    cudaGetSymbolAddress((void**)&p_dt,  g_dt);
    fp16 *p_xf, *p_win, *p_wout, *p_wx, *p_wdt, *p_xcf, *p_yf;
    cudaGetSymbolAddress((void**)&p_xf,   g_x_f);
    cudaGetSymbolAddress((void**)&p_win,  g_win);
    cudaGetSymbolAddress((void**)&p_wout, g_wout);
    cudaGetSymbolAddress((void**)&p_wx,   g_wx);
    cudaGetSymbolAddress((void**)&p_wdt,  g_wdt);
    cudaGetSymbolAddress((void**)&p_xcf,  g_xc_f);
    cudaGetSymbolAddress((void**)&p_yf,   g_y_f);

    const int M = BB * LL;  // 2048

    const int SMEM_G0 = 2 * (128 + 128) * 144;   // 73728
    const int SMEM_G1 = 2 * (64 + 128) * 144;    // 55296
    cudaFuncSetAttribute(mma_gemm<0,128,512>, cudaFuncAttributeMaxDynamicSharedMemorySize, SMEM_G0);
    cudaFuncSetAttribute(mma_gemm<1,64,256>,  cudaFuncAttributeMaxDynamicSharedMemorySize, SMEM_G1);
    cudaFuncSetAttribute(mma_gemm<2,64,256>,  cudaFuncAttributeMaxDynamicSharedMemorySize, SMEM_G1);
    cudaFuncSetAttribute(mma_gemm<3,64,256>,  cudaFuncAttributeMaxDynamicSharedMemorySize, SMEM_G1);

    // 0) fp16 converts (one launch, 9 regions; wx tail-padded, wdt row-padded)
    {
        SplitArgs a;
        auto lin = [&](int r, const float* s, fp16* d, int n4) {
            a.src[r] = s; a.dst[r] = d; a.nG[r] = n4; a.rowSrcG[r] = 1; a.rowDstG[r] = 1;
        };
        lin(0, x,        p_xf,   M * DIMM / 4);
        lin(1, W_in[0],  p_win,  2 * DI * DIMM / 4);
        lin(2, W_in[1],  p_win + (size_t)2*DI*DIMM, 2 * DI * DIMM / 4);
        lin(3, W_out[0], p_wout, DIMM * DI / 4);
        lin(4, W_out[1], p_wout + (size_t)DIMM*DI, DIMM * DI / 4);
        a.src[5] = W_x[0]; a.dst[5] = p_wx;
        a.nG[5] = NXP * DI / 4; a.rowSrcG[5] = NX * DI / 4; a.rowDstG[5] = NXP * DI / 4;
        a.src[6] = W_x[1]; a.dst[6] = p_wx + (size_t)NXP*DI;
        a.nG[6] = NXP * DI / 4; a.rowSrcG[6] = NX * DI / 4; a.rowDstG[6] = NXP * DI / 4;
        a.src[7] = W_dt[0]; a.dst[7] = p_wdt;
        a.nG[7] = DI * KDT / 4; a.rowSrcG[7] = DTR / 4; a.rowDstG[7] = KDT / 4;
        a.src[8] = W_dt[1]; a.dst[8] = p_wdt + (size_t)DI*KDT;
        a.nG[8] = DI * KDT / 4; a.rowSrcG[8] = DTR / 4; a.rowDstG[8] = KDT / 4;

        int maxn4 = 2 * DI * DIMM / 4;
        dim3 grid(cdiv(maxn4, 256), 9);
        split_all_kernel<<<grid, 256>>>(a);
    }

    // 1) xz = x(+flip) @ W_in^T  -> fp16  (512-thread CTAs, 2/SM)
    {
        dim3 grid(2 * DI / 128, M / 128, 2);
        mma_gemm<0, 128, 512><<<grid, 512, SMEM_G0>>>(
            p_xf, p_win,
            p_xz, nullptr, nullptr,
            DIMM, 2 * DI,
            0, (size_t)2*DI*DIMM, (size_t)M * 2 * DI);
    }

    // 2) conv + silu -> g_xc_f (fp16)
    {
        int n4 = 2 * BB * LL * DI / 4;
        conv_silu_kernel<<<cdiv(n4, 256), 256>>>(conv_w[0], conv_b[0], conv_w[1], conv_b[1]);
    }

    // 3) x_dbl = xc @ W_x^T  (MODE 2, split-K2, partials + reduce)
    {
        dim3 grid(2, M / 64, 2);
        mma_gemm<2, 64, 256><<<grid, 256, SMEM_G1>>>(
            p_xcf, p_wx,
            p_xdblp, nullptr, nullptr,
            DI, NX,
            (size_t)M * DI, (size_t)NXP * DI, (size_t)M * NX);
        int n4 = 2 * M * NX / 4;
        xdbl_reduce_kernel<<<cdiv(n4, 256), 256>>>();
    }

    // 4) dt = softplus(xdt @ W_dt^T + b_dt)  (MODE 3, K=64 single chunk)
    {
        dim3 grid(DI / 128, M / 64, 2);
        mma_gemm<3, 64, 256><<<grid, 256, SMEM_G1>>>(
            p_xdt, p_wdt,
            p_dt, b_dt[0], b_dt[1],
            KDT, DI,
            (size_t)M * KDT, (size_t)DI * KDT, (size_t)M * DI);
    }

    // 5) selective scan + gating -> y (fp16)
    {
        dim3 grid(DI / 32, BB, 2);
        scan_kernel<<<grid, 256>>>(A_log[0], Dvec[0], A_log[1], Dvec[1]);
    }

    // 6) out = x + y0 @ W0^T + flip(y1) @ W1^T  (MODE 1, fp32 + residual)
    {
        dim3 grid(DIMM / 128, M / 64, 1);
        mma_gemm<1, 64, 256><<<grid, 256, SMEM_G1>>>(
            p_yf, p_wout,
            out, x, nullptr,
            DI, DIMM,
            (size_t)M * DI, (size_t)DIMM * DI, 0);
    }

    (void)in_sizes; (void)n_in; (void)out_size;
}